// round 6
// baseline (speedup 1.0000x reference)
#include <cuda_runtime.h>
#include <cuda_bf16.h>
#include <math.h>
#include <stdint.h>

#define HW 16384      // 128*128
#define NB 8          // batch
#define LDA 136       // padded bf16 row stride (272B: 8 ldmatrix rows -> 8 distinct 16B groups)
#define TILEB (128 * LDA * 2)   // 34816 bytes per 128x128 bf16 tile

// Scratch (device globals; allocation inside kernel_launch is forbidden)
__device__ float g_qkv1[50331648];   // [8][384][16384]  conv1x1 output
__device__ float g_qkv2[50331648];   // [8][384][16384]  dwconv output
__device__ float g_aout[16777216];   // [8][128][16384]  attention output

// ============================ helpers ==================================
__device__ __forceinline__ uint32_t smem_u32(const void* p) {
    uint32_t a;
    asm("{ .reg .u64 t; cvta.to.shared.u64 t, %1; cvt.u32.u64 %0, t; }" : "=r"(a) : "l"(p));
    return a;
}
__device__ __forceinline__ void ldsm4(uint32_t* r, uint32_t addr) {
    asm volatile("ldmatrix.sync.aligned.m8n8.x4.shared.b16 {%0,%1,%2,%3}, [%4];"
                 : "=r"(r[0]), "=r"(r[1]), "=r"(r[2]), "=r"(r[3]) : "r"(addr));
}
__device__ __forceinline__ void mma16816(float* d, const uint32_t* a, const uint32_t* b) {
    asm volatile("mma.sync.aligned.m16n8k16.row.col.f32.bf16.bf16.f32 "
        "{%0,%1,%2,%3}, {%4,%5,%6,%7}, {%8,%9}, {%0,%1,%2,%3};"
        : "+f"(d[0]), "+f"(d[1]), "+f"(d[2]), "+f"(d[3])
        : "r"(a[0]), "r"(a[1]), "r"(a[2]), "r"(a[3]), "r"(b[0]), "r"(b[1]));
}
__device__ __forceinline__ void st_hilo(char* th, char* tl, uint32_t off, float a) {
    __nv_bfloat16 h = __float2bfloat16(a);
    *(__nv_bfloat16*)(th + off) = h;
    *(__nv_bfloat16*)(tl + off) = __float2bfloat16(a - __bfloat162float(h));
}
__device__ __forceinline__ void st_hilo_pair(char* th, char* tl, uint32_t off, float a, float b) {
    __nv_bfloat16 ah = __float2bfloat16(a), bh = __float2bfloat16(b);
    __nv_bfloat16 al = __float2bfloat16(a - __bfloat162float(ah));
    __nv_bfloat16 bl = __float2bfloat16(b - __bfloat162float(bh));
    __nv_bfloat162 ph; ph.x = ah; ph.y = bh;
    __nv_bfloat162 pl; pl.x = al; pl.y = bl;
    *(__nv_bfloat162*)(th + off) = ph;
    *(__nv_bfloat162*)(tl + off) = pl;
}

// One K=128 pass: C[128x128] += A(aBase)[128x128] * B(bBase, stored transposed [n][k])
// Warp tile 32(m) x 64(n): 2 m-tiles x 8 n-tiles of m16n8k16.
__device__ __forceinline__ void gemm_pass(uint32_t aBase, uint32_t bBase,
                                          int m0, int n0, int lane, float c[2][8][4]) {
    const int arow = lane & 15;
    const int acol = (lane >> 4) << 3;
    const int bnrow = (lane & 7) + ((lane & 16) >> 1);
    const int bkcol = lane & 8;
    #pragma unroll
    for (int ks = 0; ks < 8; ks++) {
        const int k0 = ks * 16;
        uint32_t af[2][4];
        #pragma unroll
        for (int mt = 0; mt < 2; mt++)
            ldsm4(af[mt], aBase + (uint32_t)(((m0 + mt * 16 + arow) * LDA + k0 + acol) * 2));
        uint32_t bf[8][2];
        #pragma unroll
        for (int nt = 0; nt < 4; nt++) {
            uint32_t r[4];
            ldsm4(r, bBase + (uint32_t)(((n0 + nt * 16 + bnrow) * LDA + k0 + bkcol) * 2));
            bf[2 * nt][0] = r[0]; bf[2 * nt][1] = r[1];
            bf[2 * nt + 1][0] = r[2]; bf[2 * nt + 1][1] = r[3];
        }
        #pragma unroll
        for (int mt = 0; mt < 2; mt++)
            #pragma unroll
            for (int nt = 0; nt < 8; nt++)
                mma16816(c[mt][nt], af[mt], bf[nt]);
    }
}

// ---------------------------------------------------------------------------
// conv1x1 via HMMA: Y[oc,s] = W[oc,ic] . X[ic,s] + bias.  M=128 oc, N=128 s,
// K=128 ic, hi/lo bf16 split (3 passes). grid (128 s-tiles, OC/128, B), blk 256.
// smem tiles: Wh, Wl, Xth, Xtl (Xt = X transposed [s][ic]); stage reuses Xt.
// ---------------------------------------------------------------------------
__global__ void __launch_bounds__(256, 1)
conv1x1_mma_k(const float* __restrict__ x, const float* __restrict__ w,
              const float* __restrict__ bias, float* __restrict__ y, int OCtot) {
    extern __shared__ __align__(1024) char sm[];
    char* Wh = sm;              char* Wl = sm + TILEB;
    char* Xh = sm + 2 * TILEB;  char* Xl = sm + 3 * TILEB;
    __shared__ float biassm[128];

    const int tid = threadIdx.x;
    const int wid = tid >> 5, lane = tid & 31;
    const int s0  = blockIdx.x * 128;
    const int oc0 = blockIdx.y * 128;
    const int b   = blockIdx.z;

    if (tid < 128) biassm[tid] = bias[oc0 + tid];

    // Stage W (natural [oc][ic]) and Xt (transposed [s][ic])
    {
        const float4* wg = (const float4*)(w + (size_t)oc0 * 128);
        const float4* xg = (const float4*)(x + (size_t)b * 128 * HW + s0);
        #pragma unroll
        for (int i = 0; i < 16; i++) {
            int idx4 = tid + i * 256;
            int r = idx4 >> 5, c4 = idx4 & 31;
            float4 v = wg[idx4];
            uint32_t o = (uint32_t)((r * LDA + 4 * c4) * 2);
            st_hilo_pair(Wh, Wl, o, v.x, v.y);
            st_hilo_pair(Wh, Wl, o + 4, v.z, v.w);
            float4 xv = xg[r * (HW / 4) + c4];
            int sl = 4 * c4;
            st_hilo(Xh, Xl, (uint32_t)(((sl + 0) * LDA + r) * 2), xv.x);
            st_hilo(Xh, Xl, (uint32_t)(((sl + 1) * LDA + r) * 2), xv.y);
            st_hilo(Xh, Xl, (uint32_t)(((sl + 2) * LDA + r) * 2), xv.z);
            st_hilo(Xh, Xl, (uint32_t)(((sl + 3) * LDA + r) * 2), xv.w);
        }
    }
    __syncthreads();

    const int m0 = (wid & 3) * 32, n0 = (wid >> 2) * 64;
    float c[2][8][4];
    #pragma unroll
    for (int mt = 0; mt < 2; mt++)
        #pragma unroll
        for (int nt = 0; nt < 8; nt++)
            #pragma unroll
            for (int e = 0; e < 4; e++) c[mt][nt][e] = 0.f;

    const uint32_t aWh = smem_u32(Wh), aWl = smem_u32(Wl);
    const uint32_t aXh = smem_u32(Xh), aXl = smem_u32(Xl);
    gemm_pass(aWh, aXh, m0, n0, lane, c);
    gemm_pass(aWh, aXl, m0, n0, lane, c);
    gemm_pass(aWl, aXh, m0, n0, lane, c);
    __syncthreads();   // all reads of X tiles done -> reuse as fp32 stage

    float* stage = (float*)Xh;   // [128][132]
    const int g = lane >> 2, tg = lane & 3;
    #pragma unroll
    for (int mt = 0; mt < 2; mt++) {
        int r0 = m0 + mt * 16 + g, r1 = r0 + 8;
        float b0 = biassm[r0], b1 = biassm[r1];
        #pragma unroll
        for (int nt = 0; nt < 8; nt++) {
            int col = n0 + nt * 8 + 2 * tg;
            float2 p0; p0.x = c[mt][nt][0] + b0; p0.y = c[mt][nt][1] + b0;
            *(float2*)&stage[r0 * 132 + col] = p0;
            float2 p1; p1.x = c[mt][nt][2] + b1; p1.y = c[mt][nt][3] + b1;
            *(float2*)&stage[r1 * 132 + col] = p1;
        }
    }
    __syncthreads();
    float* yb = y + ((size_t)b * OCtot + oc0) * HW + s0;
    #pragma unroll
    for (int i = 0; i < 32; i++) {
        int idx = tid + i * 256;
        int row = idx >> 6, c2 = (idx & 63) * 2;
        *(float2*)&yb[(size_t)row * HW + c2] = *(float2*)&stage[row * 132 + c2];
    }
}

// ---------------------------------------------------------------------------
// depthwise 3x3, pad 1. grid: (4 row-tiles, B*384), block 256.
// ---------------------------------------------------------------------------
__global__ void dw3x3_k(const float* __restrict__ in, const float* __restrict__ w,
                        const float* __restrict__ bias, float* __restrict__ out) {
    __shared__ float smd[34 * 128];
    const int tid = threadIdx.x;
    const int bc  = blockIdx.y;
    const int c   = bc % 384;
    const int h0  = blockIdx.x * 32;

    const float* src = in + (size_t)bc * HW;
    for (int idx = tid; idx < 34 * 128; idx += 256) {
        int r = idx >> 7, col = idx & 127;
        int h = h0 - 1 + r;
        smd[idx] = (h >= 0 && h < 128) ? src[h * 128 + col] : 0.f;
    }
    float wv[9];
    #pragma unroll
    for (int i = 0; i < 9; i++) wv[i] = w[c * 9 + i];
    const float bi = bias[c];
    __syncthreads();

    float* dst = out + (size_t)bc * HW + h0 * 128;
    for (int idx = tid; idx < 32 * 128; idx += 256) {
        int r = idx >> 7, col = idx & 127;
        float acc = bi;
        #pragma unroll
        for (int dy = 0; dy < 3; dy++) {
            #pragma unroll
            for (int dx = 0; dx < 3; dx++) {
                int cc = col + dx - 1;
                float v = (cc >= 0 && cc < 128) ? smd[(r + dy) * 128 + cc] : 0.f;
                acc = fmaf(wv[dy * 3 + dx], v, acc);
            }
        }
        dst[idx] = acc;
    }
}

// ---------------------------------------------------------------------------
// Attention per (b,head,c) slice; one CTA each (1024 CTAs), block 256, HMMA.
//   GEMM1: Lt[k][j] = sum_i Kt[k][i]*Qt[j][i]      (A=Kt tiles, Bt=Qt tiles)
//   scale by rnk[k]*rqs[j] (temp folded in), exp in regs, per-row (k) sums via
//   shfl + 2-warp smem combine; P^T[k][j]=exp stored hi/lo into dead Kt space.
//   GEMM2: D2[i][k] = sum_j V[i][j]*P[j][k]        (A=V tiles, Bt=Pt tiles)
//   scaled by sinv[k] in epilogue. smem: 6 tiles = 208896 B.
// ---------------------------------------------------------------------------
__global__ void __launch_bounds__(256, 1)
attn_mma_k(const float* __restrict__ qkv, const float* __restrict__ temp,
           float* __restrict__ out) {
    extern __shared__ __align__(1024) char sm[];
    char* Qh = sm;              char* Ql = sm + TILEB;
    char* Kh = sm + 2 * TILEB;  char* Kl = sm + 3 * TILEB;
    char* Vh = sm + 4 * TILEB;  char* Vl = sm + 5 * TILEB;
    __shared__ float rqs[128], rnk[128], rowsum[2][128], sinv[128];

    const int tid = threadIdx.x;
    const int wid = tid >> 5, lane = tid & 31;
    const int cid = blockIdx.x;
    const int qc  = cid & 127;
    const int b   = cid >> 7;
    const int hd  = qc >> 5;

    const float4* qg = (const float4*)(qkv + ((size_t)b * 384 + qc) * HW);
    const float4* kg = (const float4*)(qkv + ((size_t)b * 384 + qc + 128) * HW);
    const float4* vg = (const float4*)(qkv + ((size_t)b * 384 + qc + 256) * HW);

    // Stage: Qt[w][h], Kt[w][h] (transposed), V[h][w] (natural), hi/lo split
    #pragma unroll
    for (int i = 0; i < 16; i++) {
        int idx4 = tid + i * 256;
        int h = idx4 >> 5, w4 = 4 * (idx4 & 31);
        float4 q = qg[idx4], k = kg[idx4], v = vg[idx4];
        st_hilo(Qh, Ql, (uint32_t)(((w4 + 0) * LDA + h) * 2), q.x);
        st_hilo(Qh, Ql, (uint32_t)(((w4 + 1) * LDA + h) * 2), q.y);
        st_hilo(Qh, Ql, (uint32_t)(((w4 + 2) * LDA + h) * 2), q.z);
        st_hilo(Qh, Ql, (uint32_t)(((w4 + 3) * LDA + h) * 2), q.w);
        st_hilo(Kh, Kl, (uint32_t)(((w4 + 0) * LDA + h) * 2), k.x);
        st_hilo(Kh, Kl, (uint32_t)(((w4 + 1) * LDA + h) * 2), k.y);
        st_hilo(Kh, Kl, (uint32_t)(((w4 + 2) * LDA + h) * 2), k.z);
        st_hilo(Kh, Kl, (uint32_t)(((w4 + 3) * LDA + h) * 2), k.w);
        st_hilo_pair(Vh, Vl, (uint32_t)((h * LDA + w4) * 2), v.x, v.y);
        st_hilo_pair(Vh, Vl, (uint32_t)((h * LDA + w4 + 2) * 2), v.z, v.w);
    }
    __syncthreads();

    // Column L2 norms (rows of the transposed tiles), fp32 from hi+lo
    {
        const float tp = temp[hd];
        if (tid < 128) {
            float s = 0.f;
            #pragma unroll 4
            for (int i = 0; i < 128; i++) {
                uint32_t o = (uint32_t)((tid * LDA + i) * 2);
                float xv = __bfloat162float(*(const __nv_bfloat16*)(Qh + o)) +
                           __bfloat162float(*(const __nv_bfloat16*)(Ql + o));
                s = fmaf(xv, xv, s);
            }
            rqs[tid] = tp / fmaxf(sqrtf(s), 1e-12f);
        } else {
            int wr = tid - 128;
            float s = 0.f;
            #pragma unroll 4
            for (int i = 0; i < 128; i++) {
                uint32_t o = (uint32_t)((wr * LDA + i) * 2);
                float xv = __bfloat162float(*(const __nv_bfloat16*)(Kh + o)) +
                           __bfloat162float(*(const __nv_bfloat16*)(Kl + o));
                s = fmaf(xv, xv, s);
            }
            rnk[wr] = 1.f / fmaxf(sqrtf(s), 1e-12f);
        }
    }
    __syncthreads();

    const int m0 = (wid & 3) * 32, n0 = (wid >> 2) * 64;
    const uint32_t aQh = smem_u32(Qh), aQl = smem_u32(Ql);
    const uint32_t aKh = smem_u32(Kh), aKl = smem_u32(Kl);
    const uint32_t aVh = smem_u32(Vh), aVl = smem_u32(Vl);

    float c[2][8][4];
    #pragma unroll
    for (int mt = 0; mt < 2; mt++)
        #pragma unroll
        for (int nt = 0; nt < 8; nt++)
            #pragma unroll
            for (int e = 0; e < 4; e++) c[mt][nt][e] = 0.f;

    // GEMM1
    gemm_pass(aKh, aQh, m0, n0, lane, c);
    gemm_pass(aKh, aQl, m0, n0, lane, c);
    gemm_pass(aKl, aQh, m0, n0, lane, c);

    // scale + exp in regs, row-partial sums
    const int g = lane >> 2, tg = lane & 3;
    float rs[4] = {0.f, 0.f, 0.f, 0.f};
    #pragma unroll
    for (int mt = 0; mt < 2; mt++) {
        int r0 = m0 + mt * 16 + g, r1 = r0 + 8;
        float k0s = rnk[r0], k1s = rnk[r1];
        #pragma unroll
        for (int nt = 0; nt < 8; nt++) {
            int j0 = n0 + nt * 8 + 2 * tg;
            float q0 = rqs[j0], q1 = rqs[j0 + 1];
            float e0 = __expf(c[mt][nt][0] * k0s * q0);
            float e1 = __expf(c[mt][nt][1] * k0s * q1);
            float e2 = __expf(c[mt][nt][2] * k1s * q0);
            float e3 = __expf(c[mt][nt][3] * k1s * q1);
            c[mt][nt][0] = e0; c[mt][nt][1] = e1;
            c[mt][nt][2] = e2; c[mt][nt][3] = e3;
            rs[2 * mt] += e0 + e1;
            rs[2 * mt + 1] += e2 + e3;
        }
    }
    __syncthreads();   // all GEMM1 reads of K/Q tiles done

    // store P^T into K tile space (hi/lo); finish row sums
    #pragma unroll
    for (int mt = 0; mt < 2; mt++) {
        int r0 = m0 + mt * 16 + g, r1 = r0 + 8;
        #pragma unroll
        for (int nt = 0; nt < 8; nt++) {
            int j0 = n0 + nt * 8 + 2 * tg;
            st_hilo_pair(Kh, Kl, (uint32_t)((r0 * LDA + j0) * 2), c[mt][nt][0], c[mt][nt][1]);
            st_hilo_pair(Kh, Kl, (uint32_t)((r1 * LDA + j0) * 2), c[mt][nt][2], c[mt][nt][3]);
        }
    }
    #pragma unroll
    for (int i = 0; i < 4; i++) {
        rs[i] += __shfl_xor_sync(0xFFFFFFFFu, rs[i], 1);
        rs[i] += __shfl_xor_sync(0xFFFFFFFFu, rs[i], 2);
    }
    if (tg == 0) {
        int grp = n0 >> 6;
        rowsum[grp][m0 + g]      = rs[0];
        rowsum[grp][m0 + 8 + g]  = rs[1];
        rowsum[grp][m0 + 16 + g] = rs[2];
        rowsum[grp][m0 + 24 + g] = rs[3];
    }
    __syncthreads();
    if (tid < 128) sinv[tid] = 1.f / (rowsum[0][tid] + rowsum[1][tid]);

    // GEMM2
    #pragma unroll
    for (int mt = 0; mt < 2; mt++)
        #pragma unroll
        for (int nt = 0; nt < 8; nt++)
            #pragma unroll
            for (int e = 0; e < 4; e++) c[mt][nt][e] = 0.f;
    gemm_pass(aVh, aKh, m0, n0, lane, c);
    gemm_pass(aVh, aKl, m0, n0, lane, c);
    gemm_pass(aVl, aKh, m0, n0, lane, c);
    __syncthreads();   // P reads done; sinv visible; reuse Q tiles as stage

    float* stage = (float*)Qh;   // [128][132]
    #pragma unroll
    for (int mt = 0; mt < 2; mt++) {
        int r0 = m0 + mt * 16 + g, r1 = r0 + 8;
        #pragma unroll
        for (int nt = 0; nt < 8; nt++) {
            int col = n0 + nt * 8 + 2 * tg;
            float s0 = sinv[col], s1 = sinv[col + 1];
            float2 p0; p0.x = c[mt][nt][0] * s0; p0.y = c[mt][nt][1] * s1;
            *(float2*)&stage[r0 * 132 + col] = p0;
            float2 p1; p1.x = c[mt][nt][2] * s0; p1.y = c[mt][nt][3] * s1;
            *(float2*)&stage[r1 * 132 + col] = p1;
        }
    }
    __syncthreads();
    float* og = out + ((size_t)b * 128 + qc) * HW;
    #pragma unroll
    for (int i = 0; i < 32; i++) {
        int idx = tid + i * 256;
        int row = idx >> 6, c2 = (idx & 63) * 2;
        *(float2*)&og[row * 128 + c2] = *(float2*)&stage[row * 132 + c2];
    }
}

// ---------------------------------------------------------------------------
extern "C" void kernel_launch(void* const* d_in, const int* in_sizes, int n_in,
                              void* d_out, int out_size) {
    const float* x      = (const float*)d_in[0];
    const float* qkv_w  = (const float*)d_in[1];
    const float* qkv_b  = (const float*)d_in[2];
    const float* dw_w   = (const float*)d_in[3];
    const float* dw_b   = (const float*)d_in[4];
    const float* proj_w = (const float*)d_in[5];
    const float* proj_b = (const float*)d_in[6];
    const float* temp   = (const float*)d_in[7];
    float* out = (float*)d_out;

    void *p1, *p2, *p3;
    cudaGetSymbolAddress(&p1, g_qkv1);
    cudaGetSymbolAddress(&p2, g_qkv2);
    cudaGetSymbolAddress(&p3, g_aout);
    float* qkv1 = (float*)p1;
    float* qkv2 = (float*)p2;
    float* aout = (float*)p3;

    const int conv_smem = 4 * TILEB;   // 139264
    const int attn_smem = 6 * TILEB;   // 208896
    cudaFuncSetAttribute(conv1x1_mma_k, cudaFuncAttributeMaxDynamicSharedMemorySize, conv_smem);
    cudaFuncSetAttribute(attn_mma_k,    cudaFuncAttributeMaxDynamicSharedMemorySize, attn_smem);

    // 1) qkv = conv1x1(x)
    conv1x1_mma_k<<<dim3(128, 3, NB), 256, conv_smem>>>(x, qkv_w, qkv_b, qkv1, 384);
    // 2) qkv = dwconv3x3(qkv)
    dw3x3_k<<<dim3(4, NB * 384), 256>>>(qkv1, dw_w, dw_b, qkv2);
    // 3) transposed attention per (b, head, c)
    attn_mma_k<<<dim3(1024), 256, attn_smem>>>(qkv2, temp, aout);
    // 4) out = conv1x1(attn_out)
    conv1x1_mma_k<<<dim3(128, 1, NB), 256, conv_smem>>>(aout, proj_w, proj_b, out, 128);
}

// round 7
// speedup vs baseline: 1.4421x; 1.4421x over previous
#include <cuda_runtime.h>
#include <cuda_bf16.h>
#include <math.h>
#include <stdint.h>

#define HW 16384      // 128*128
#define NB 8          // batch
#define LDA 136       // padded bf16 row stride (272B -> conflict-free ldmatrix rows)
#define TILEB (128 * LDA * 2)   // 34816 bytes per 128x128 bf16 tile

// Scratch (device globals; allocation inside kernel_launch is forbidden)
__device__ float g_qkv1[50331648];   // [8][384][16384]  conv1x1 output
__device__ float g_qkv2[50331648];   // [8][384][16384]  dwconv output
__device__ float g_aout[16777216];   // [8][128][16384]  attention output

// ============================ helpers ==================================
__device__ __forceinline__ uint32_t smem_u32(const void* p) {
    uint32_t a;
    asm("{ .reg .u64 t; cvta.to.shared.u64 t, %1; cvt.u32.u64 %0, t; }" : "=r"(a) : "l"(p));
    return a;
}
__device__ __forceinline__ void ldsm4(uint32_t* r, uint32_t addr) {
    asm volatile("ldmatrix.sync.aligned.m8n8.x4.shared.b16 {%0,%1,%2,%3}, [%4];"
                 : "=r"(r[0]), "=r"(r[1]), "=r"(r[2]), "=r"(r[3]) : "r"(addr));
}
__device__ __forceinline__ void ldsm4_t(uint32_t* r, uint32_t addr) {
    asm volatile("ldmatrix.sync.aligned.m8n8.x4.trans.shared.b16 {%0,%1,%2,%3}, [%4];"
                 : "=r"(r[0]), "=r"(r[1]), "=r"(r[2]), "=r"(r[3]) : "r"(addr));
}
__device__ __forceinline__ void mma16816(float* d, const uint32_t* a, const uint32_t* b) {
    asm volatile("mma.sync.aligned.m16n8k16.row.col.f32.bf16.bf16.f32 "
        "{%0,%1,%2,%3}, {%4,%5,%6,%7}, {%8,%9}, {%0,%1,%2,%3};"
        : "+f"(d[0]), "+f"(d[1]), "+f"(d[2]), "+f"(d[3])
        : "r"(a[0]), "r"(a[1]), "r"(a[2]), "r"(a[3]), "r"(b[0]), "r"(b[1]));
}
__device__ __forceinline__ float bf2f(const void* p) {
    return __bfloat162float(*(const __nv_bfloat16*)p);
}
__device__ __forceinline__ void st_hilo_pair(char* th, char* tl, uint32_t off, float a, float b) {
    __nv_bfloat16 ah = __float2bfloat16(a), bh = __float2bfloat16(b);
    __nv_bfloat16 al = __float2bfloat16(a - __bfloat162float(ah));
    __nv_bfloat16 bl = __float2bfloat16(b - __bfloat162float(bh));
    __nv_bfloat162 ph; ph.x = ah; ph.y = bh;
    __nv_bfloat162 pl; pl.x = al; pl.y = bl;
    *(__nv_bfloat162*)(th + off) = ph;
    *(__nv_bfloat162*)(tl + off) = pl;
}

// One K=128 pass: C[warp 32x32] += op(A) * op(B).
// AT=0: A stored [m][k] row-major. AT=1: A stored [k][m] (trans ldmatrix).
// BT=0: B stored [n][k].           BT=1: B stored [k][n] (trans ldmatrix).
template<int AT, int BT>
__device__ __forceinline__ void gemm_pass(uint32_t aBase, uint32_t bBase,
                                          int m0, int n0, int lane, float c[2][4][4]) {
    #pragma unroll
    for (int ks = 0; ks < 8; ks++) {
        const int k0 = ks * 16;
        uint32_t af[2][4];
        #pragma unroll
        for (int mt = 0; mt < 2; mt++) {
            if (AT) {
                int krow = k0 + (lane & 7) + ((lane & 16) >> 1);
                int mcol = m0 + mt * 16 + (lane & 8);
                ldsm4_t(af[mt], aBase + (uint32_t)((krow * LDA + mcol) * 2));
            } else {
                int arow = m0 + mt * 16 + (lane & 15);
                int acol = k0 + ((lane >> 4) << 3);
                ldsm4(af[mt], aBase + (uint32_t)((arow * LDA + acol) * 2));
            }
        }
        uint32_t bf[4][2];
        #pragma unroll
        for (int nb = 0; nb < 2; nb++) {
            uint32_t r[4];
            if (BT) {
                int krow = k0 + (lane & 7) + (lane & 8);
                int ncol = n0 + nb * 16 + ((lane & 16) >> 1);
                ldsm4_t(r, bBase + (uint32_t)((krow * LDA + ncol) * 2));
            } else {
                int nrow = n0 + nb * 16 + (lane & 7) + ((lane & 16) >> 1);
                int kcol = k0 + (lane & 8);
                ldsm4(r, bBase + (uint32_t)((nrow * LDA + kcol) * 2));
            }
            bf[2 * nb][0] = r[0];     bf[2 * nb][1] = r[1];
            bf[2 * nb + 1][0] = r[2]; bf[2 * nb + 1][1] = r[3];
        }
        #pragma unroll
        for (int mt = 0; mt < 2; mt++)
            #pragma unroll
            for (int nt = 0; nt < 4; nt++)
                mma16816(c[mt][nt], af[mt], bf[nt]);
    }
}

// ---------------------------------------------------------------------------
// conv1x1 via HMMA: Y[oc,s] = W[oc,ic] . X[ic,s] + bias.
// All staging NATURAL: W [oc][ic] (A non-trans), X [ic][s] (B trans).
// grid (128 s-tiles, OC/128, B), block 512 (16 warps, 32x32 warp tiles).
// ---------------------------------------------------------------------------
__global__ void __launch_bounds__(512, 1)
conv1x1_mma_k(const float* __restrict__ x, const float* __restrict__ w,
              const float* __restrict__ bias, float* __restrict__ y, int OCtot) {
    extern __shared__ __align__(1024) char sm[];
    char* Wh = sm;              char* Wl = sm + TILEB;
    char* Xh = sm + 2 * TILEB;  char* Xl = sm + 3 * TILEB;
    __shared__ float biassm[128];

    const int tid = threadIdx.x;
    const int wid = tid >> 5, lane = tid & 31;
    const int s0  = blockIdx.x * 128;
    const int oc0 = blockIdx.y * 128;
    const int b   = blockIdx.z;

    if (tid < 128) biassm[tid] = bias[oc0 + tid];

    {
        const float4* wg = (const float4*)(w + (size_t)oc0 * 128);
        const float4* xg = (const float4*)(x + (size_t)b * 128 * HW + s0);
        #pragma unroll
        for (int i = 0; i < 8; i++) {
            int idx4 = tid + i * 512;
            int r = idx4 >> 5, c4 = idx4 & 31;
            uint32_t o = (uint32_t)((r * LDA + 4 * c4) * 2);
            float4 v = wg[idx4];
            st_hilo_pair(Wh, Wl, o, v.x, v.y);
            st_hilo_pair(Wh, Wl, o + 4, v.z, v.w);
            float4 xv = xg[r * (HW / 4) + c4];
            st_hilo_pair(Xh, Xl, o, xv.x, xv.y);
            st_hilo_pair(Xh, Xl, o + 4, xv.z, xv.w);
        }
    }
    __syncthreads();

    const int m0 = (wid & 3) * 32, n0 = (wid >> 2) * 32;
    float c[2][4][4];
    #pragma unroll
    for (int mt = 0; mt < 2; mt++)
        #pragma unroll
        for (int nt = 0; nt < 4; nt++)
            #pragma unroll
            for (int e = 0; e < 4; e++) c[mt][nt][e] = 0.f;

    const uint32_t aWh = smem_u32(Wh), aWl = smem_u32(Wl);
    const uint32_t aXh = smem_u32(Xh), aXl = smem_u32(Xl);
    gemm_pass<0, 1>(aWh, aXh, m0, n0, lane, c);
    gemm_pass<0, 1>(aWh, aXl, m0, n0, lane, c);
    gemm_pass<0, 1>(aWl, aXh, m0, n0, lane, c);
    __syncthreads();   // all reads of X tiles done -> reuse as fp32 stage

    float* stage = (float*)Xh;   // [128][132]
    const int g = lane >> 2, tg = lane & 3;
    #pragma unroll
    for (int mt = 0; mt < 2; mt++) {
        int r0 = m0 + mt * 16 + g, r1 = r0 + 8;
        float b0 = biassm[r0], b1 = biassm[r1];
        #pragma unroll
        for (int nt = 0; nt < 4; nt++) {
            int col = n0 + nt * 8 + 2 * tg;
            float2 p0; p0.x = c[mt][nt][0] + b0; p0.y = c[mt][nt][1] + b0;
            *(float2*)&stage[r0 * 132 + col] = p0;
            float2 p1; p1.x = c[mt][nt][2] + b1; p1.y = c[mt][nt][3] + b1;
            *(float2*)&stage[r1 * 132 + col] = p1;
        }
    }
    __syncthreads();
    float* yb = y + ((size_t)b * OCtot + oc0) * HW + s0;
    #pragma unroll
    for (int i = 0; i < 16; i++) {
        int idx = tid + i * 512;
        int row = idx >> 6, c2 = (idx & 63) * 2;
        *(float2*)&yb[(size_t)row * HW + c2] = *(float2*)&stage[row * 132 + c2];
    }
}

// ---------------------------------------------------------------------------
// depthwise 3x3, pad 1. grid: (4 row-tiles, B*384), block 256.
// ---------------------------------------------------------------------------
__global__ void dw3x3_k(const float* __restrict__ in, const float* __restrict__ w,
                        const float* __restrict__ bias, float* __restrict__ out) {
    __shared__ float smd[34 * 128];
    const int tid = threadIdx.x;
    const int bc  = blockIdx.y;
    const int c   = bc % 384;
    const int h0  = blockIdx.x * 32;

    const float* src = in + (size_t)bc * HW;
    for (int idx = tid; idx < 34 * 128; idx += 256) {
        int r = idx >> 7, col = idx & 127;
        int h = h0 - 1 + r;
        smd[idx] = (h >= 0 && h < 128) ? src[h * 128 + col] : 0.f;
    }
    float wv[9];
    #pragma unroll
    for (int i = 0; i < 9; i++) wv[i] = w[c * 9 + i];
    const float bi = bias[c];
    __syncthreads();

    float* dst = out + (size_t)bc * HW + h0 * 128;
    for (int idx = tid; idx < 32 * 128; idx += 256) {
        int r = idx >> 7, col = idx & 127;
        float acc = bi;
        #pragma unroll
        for (int dy = 0; dy < 3; dy++) {
            #pragma unroll
            for (int dx = 0; dx < 3; dx++) {
                int cc = col + dx - 1;
                float v = (cc >= 0 && cc < 128) ? smd[(r + dy) * 128 + cc] : 0.f;
                acc = fmaf(wv[dy * 3 + dx], v, acc);
            }
        }
        dst[idx] = acc;
    }
}

// ---------------------------------------------------------------------------
// Attention per (b,head,c) slice; one CTA each (1024), block 512, HMMA.
// Staging NATURAL: Q,K,V as [i][w].
//   GEMM1: Lt[k][j] = sum_i K[i][k]*Q[i][j]   (A trans from K, B trans from Q)
//   scale rnk[k]*rqs[j] (temp folded), exp in regs, row sums via shfl+smem,
//   P^T[k][j] stored hi/lo into K tiles (natural rows).
//   GEMM2: D2[i][k] = sum_j V[i][j]*P[j][k]   (A non-trans V, B non-trans Pt)
//   scaled by sinv[k] in epilogue.
// ---------------------------------------------------------------------------
__global__ void __launch_bounds__(512, 1)
attn_mma_k(const float* __restrict__ qkv, const float* __restrict__ temp,
           float* __restrict__ out) {
    extern __shared__ __align__(1024) char sm[];
    char* Qh = sm;              char* Ql = sm + TILEB;
    char* Kh = sm + 2 * TILEB;  char* Kl = sm + 3 * TILEB;
    char* Vh = sm + 4 * TILEB;  char* Vl = sm + 5 * TILEB;
    __shared__ float rqs[128], rnk[128], sinv[128];
    __shared__ float psum[4][128], rowsum[4][128];

    const int tid = threadIdx.x;
    const int wid = tid >> 5, lane = tid & 31;
    const int cid = blockIdx.x;
    const int qc  = cid & 127;
    const int b   = cid >> 7;
    const int hd  = qc >> 5;

    const float4* qg = (const float4*)(qkv + ((size_t)b * 384 + qc) * HW);
    const float4* kg = (const float4*)(qkv + ((size_t)b * 384 + qc + 128) * HW);
    const float4* vg = (const float4*)(qkv + ((size_t)b * 384 + qc + 256) * HW);

    #pragma unroll
    for (int i = 0; i < 8; i++) {
        int idx4 = tid + i * 512;
        int h = idx4 >> 5, w4 = 4 * (idx4 & 31);
        uint32_t o = (uint32_t)((h * LDA + w4) * 2);
        float4 q = qg[idx4], k = kg[idx4], v = vg[idx4];
        st_hilo_pair(Qh, Ql, o, q.x, q.y);
        st_hilo_pair(Qh, Ql, o + 4, q.z, q.w);
        st_hilo_pair(Kh, Kl, o, k.x, k.y);
        st_hilo_pair(Kh, Kl, o + 4, k.z, k.w);
        st_hilo_pair(Vh, Vl, o, v.x, v.y);
        st_hilo_pair(Vh, Vl, o + 4, v.z, v.w);
    }
    __syncthreads();

    // Column L2 norms over i, parallel across 4 groups of 128 threads
    {
        int col = tid & 127, gq = tid >> 7;
        const char* bh = (gq < 2) ? Qh : Kh;
        const char* bl = (gq < 2) ? Ql : Kl;
        int i0 = (gq & 1) * 64;
        float s = 0.f;
        #pragma unroll 8
        for (int i = 0; i < 64; i++) {
            uint32_t o = (uint32_t)(((i0 + i) * LDA + col) * 2);
            float xv = bf2f(bh + o) + bf2f(bl + o);
            s = fmaf(xv, xv, s);
        }
        psum[gq][col] = s;
    }
    __syncthreads();
    {
        const float tp = temp[hd];
        if (tid < 128)
            rqs[tid] = tp / fmaxf(sqrtf(psum[0][tid] + psum[1][tid]), 1e-12f);
        else if (tid < 256) {
            int c2 = tid - 128;
            rnk[c2] = 1.f / fmaxf(sqrtf(psum[2][c2] + psum[3][c2]), 1e-12f);
        }
    }
    __syncthreads();

    const int m0 = (wid & 3) * 32, n0 = (wid >> 2) * 32;
    const uint32_t aQh = smem_u32(Qh), aQl = smem_u32(Ql);
    const uint32_t aKh = smem_u32(Kh), aKl = smem_u32(Kl);
    const uint32_t aVh = smem_u32(Vh), aVl = smem_u32(Vl);

    float c[2][4][4];
    #pragma unroll
    for (int mt = 0; mt < 2; mt++)
        #pragma unroll
        for (int nt = 0; nt < 4; nt++)
            #pragma unroll
            for (int e = 0; e < 4; e++) c[mt][nt][e] = 0.f;

    // GEMM1: A trans from K [i][w], B trans from Q [i][w]
    gemm_pass<1, 1>(aKh, aQh, m0, n0, lane, c);
    gemm_pass<1, 1>(aKh, aQl, m0, n0, lane, c);
    gemm_pass<1, 1>(aKl, aQh, m0, n0, lane, c);

    // scale + exp in regs, row-partial sums
    const int g = lane >> 2, tg = lane & 3;
    float rs[4] = {0.f, 0.f, 0.f, 0.f};
    #pragma unroll
    for (int mt = 0; mt < 2; mt++) {
        int r0 = m0 + mt * 16 + g, r1 = r0 + 8;
        float k0s = rnk[r0], k1s = rnk[r1];
        #pragma unroll
        for (int nt = 0; nt < 4; nt++) {
            int j0 = n0 + nt * 8 + 2 * tg;
            float q0 = rqs[j0], q1 = rqs[j0 + 1];
            float e0 = __expf(c[mt][nt][0] * k0s * q0);
            float e1 = __expf(c[mt][nt][1] * k0s * q1);
            float e2 = __expf(c[mt][nt][2] * k1s * q0);
            float e3 = __expf(c[mt][nt][3] * k1s * q1);
            c[mt][nt][0] = e0; c[mt][nt][1] = e1;
            c[mt][nt][2] = e2; c[mt][nt][3] = e3;
            rs[2 * mt] += e0 + e1;
            rs[2 * mt + 1] += e2 + e3;
        }
    }
    __syncthreads();   // all GEMM1 reads of K/Q tiles done

    // store P^T into K tile space (natural rows k); finish row sums
    #pragma unroll
    for (int mt = 0; mt < 2; mt++) {
        int r0 = m0 + mt * 16 + g, r1 = r0 + 8;
        #pragma unroll
        for (int nt = 0; nt < 4; nt++) {
            int j0 = n0 + nt * 8 + 2 * tg;
            st_hilo_pair(Kh, Kl, (uint32_t)((r0 * LDA + j0) * 2), c[mt][nt][0], c[mt][nt][1]);
            st_hilo_pair(Kh, Kl, (uint32_t)((r1 * LDA + j0) * 2), c[mt][nt][2], c[mt][nt][3]);
        }
    }
    #pragma unroll
    for (int i = 0; i < 4; i++) {
        rs[i] += __shfl_xor_sync(0xFFFFFFFFu, rs[i], 1);
        rs[i] += __shfl_xor_sync(0xFFFFFFFFu, rs[i], 2);
    }
    if (tg == 0) {
        int grp = wid >> 2;
        rowsum[grp][m0 + g]      = rs[0];
        rowsum[grp][m0 + 8 + g]  = rs[1];
        rowsum[grp][m0 + 16 + g] = rs[2];
        rowsum[grp][m0 + 24 + g] = rs[3];
    }
    __syncthreads();
    if (tid < 128)
        sinv[tid] = 1.f / (rowsum[0][tid] + rowsum[1][tid] + rowsum[2][tid] + rowsum[3][tid]);

    // GEMM2: A non-trans V [i][j], B non-trans Pt [k][j]
    #pragma unroll
    for (int mt = 0; mt < 2; mt++)
        #pragma unroll
        for (int nt = 0; nt < 4; nt++)
            #pragma unroll
            for (int e = 0; e < 4; e++) c[mt][nt][e] = 0.f;
    gemm_pass<0, 0>(aVh, aKh, m0, n0, lane, c);
    gemm_pass<0, 0>(aVh, aKl, m0, n0, lane, c);
    gemm_pass<0, 0>(aVl, aKh, m0, n0, lane, c);
    __syncthreads();   // sinv visible; Q tiles free for staging

    float* stage = (float*)Qh;   // [128][132]
    #pragma unroll
    for (int mt = 0; mt < 2; mt++) {
        int r0 = m0 + mt * 16 + g, r1 = r0 + 8;
        #pragma unroll
        for (int nt = 0; nt < 4; nt++) {
            int col = n0 + nt * 8 + 2 * tg;
            float s0 = sinv[col], s1 = sinv[col + 1];
            float2 p0; p0.x = c[mt][nt][0] * s0; p0.y = c[mt][nt][1] * s1;
            *(float2*)&stage[r0 * 132 + col] = p0;
            float2 p1; p1.x = c[mt][nt][2] * s0; p1.y = c[mt][nt][3] * s1;
            *(float2*)&stage[r1 * 132 + col] = p1;
        }
    }
    __syncthreads();
    float* og = out + ((size_t)b * 128 + qc) * HW;
    #pragma unroll
    for (int i = 0; i < 16; i++) {
        int idx = tid + i * 512;
        int row = idx >> 6, c2 = (idx & 63) * 2;
        *(float2*)&og[row * 128 + c2] = *(float2*)&stage[row * 132 + c2];
    }
}

// ---------------------------------------------------------------------------
extern "C" void kernel_launch(void* const* d_in, const int* in_sizes, int n_in,
                              void* d_out, int out_size) {
    const float* x      = (const float*)d_in[0];
    const float* qkv_w  = (const float*)d_in[1];
    const float* qkv_b  = (const float*)d_in[2];
    const float* dw_w   = (const float*)d_in[3];
    const float* dw_b   = (const float*)d_in[4];
    const float* proj_w = (const float*)d_in[5];
    const float* proj_b = (const float*)d_in[6];
    const float* temp   = (const float*)d_in[7];
    float* out = (float*)d_out;

    void *p1, *p2, *p3;
    cudaGetSymbolAddress(&p1, g_qkv1);
    cudaGetSymbolAddress(&p2, g_qkv2);
    cudaGetSymbolAddress(&p3, g_aout);
    float* qkv1 = (float*)p1;
    float* qkv2 = (float*)p2;
    float* aout = (float*)p3;

    const int conv_smem = 4 * TILEB;   // 139264
    const int attn_smem = 6 * TILEB;   // 208896
    cudaFuncSetAttribute(conv1x1_mma_k, cudaFuncAttributeMaxDynamicSharedMemorySize, conv_smem);
    cudaFuncSetAttribute(attn_mma_k,    cudaFuncAttributeMaxDynamicSharedMemorySize, attn_smem);

    // 1) qkv = conv1x1(x)
    conv1x1_mma_k<<<dim3(128, 3, NB), 512, conv_smem>>>(x, qkv_w, qkv_b, qkv1, 384);
    // 2) qkv = dwconv3x3(qkv)
    dw3x3_k<<<dim3(4, NB * 384), 256>>>(qkv1, dw_w, dw_b, qkv2);
    // 3) transposed attention per (b, head, c)
    attn_mma_k<<<dim3(1024), 512, attn_smem>>>(qkv2, temp, aout);
    // 4) out = conv1x1(attn_out)
    conv1x1_mma_k<<<dim3(128, 1, NB), 512, conv_smem>>>(aout, proj_w, proj_b, out, 128);
}

// round 11
// speedup vs baseline: 1.5829x; 1.0976x over previous
#include <cuda_runtime.h>
#include <cuda_bf16.h>
#include <math.h>
#include <stdint.h>

#define HW 16384      // 128*128
#define NB 8          // batch
#define LDA 136       // padded bf16 row stride (272B -> conflict-free ldmatrix rows)
#define TILEB (128 * LDA * 2)   // 34816 bytes per 128x128 bf16 tile

// Scratch (device globals; allocation inside kernel_launch is forbidden)
__device__ float g_qkv1[50331648];            // [8][384][16384] conv1x1 out (fp32)
__device__ __nv_bfloat16 g_q2h[50331648];     // dwconv out hi
__device__ __nv_bfloat16 g_q2l[50331648];     // dwconv out lo
__device__ __nv_bfloat16 g_aoh[16777216];     // attn out hi
__device__ __nv_bfloat16 g_aol[16777216];     // attn out lo

// ============================ helpers ==================================
__device__ __forceinline__ uint32_t smem_u32(const void* p) {
    uint32_t a;
    asm("{ .reg .u64 t; cvta.to.shared.u64 t, %1; cvt.u32.u64 %0, t; }" : "=r"(a) : "l"(p));
    return a;
}
__device__ __forceinline__ void ldsm4(uint32_t* r, uint32_t addr) {
    asm volatile("ldmatrix.sync.aligned.m8n8.x4.shared.b16 {%0,%1,%2,%3}, [%4];"
                 : "=r"(r[0]), "=r"(r[1]), "=r"(r[2]), "=r"(r[3]) : "r"(addr));
}
__device__ __forceinline__ void ldsm4_t(uint32_t* r, uint32_t addr) {
    asm volatile("ldmatrix.sync.aligned.m8n8.x4.trans.shared.b16 {%0,%1,%2,%3}, [%4];"
                 : "=r"(r[0]), "=r"(r[1]), "=r"(r[2]), "=r"(r[3]) : "r"(addr));
}
__device__ __forceinline__ void mma16816(float* d, const uint32_t* a, const uint32_t* b) {
    asm volatile("mma.sync.aligned.m16n8k16.row.col.f32.bf16.bf16.f32 "
        "{%0,%1,%2,%3}, {%4,%5,%6,%7}, {%8,%9}, {%0,%1,%2,%3};"
        : "+f"(d[0]), "+f"(d[1]), "+f"(d[2]), "+f"(d[3])
        : "r"(a[0]), "r"(a[1]), "r"(a[2]), "r"(a[3]), "r"(b[0]), "r"(b[1]));
}
__device__ __forceinline__ float bf2f(const void* p) {
    return __bfloat162float(*(const __nv_bfloat16*)p);
}
__device__ __forceinline__ void st_hilo_pair(char* th, char* tl, uint32_t off, float a, float b) {
    __nv_bfloat16 ah = __float2bfloat16(a), bh = __float2bfloat16(b);
    __nv_bfloat16 al = __float2bfloat16(a - __bfloat162float(ah));
    __nv_bfloat16 bl = __float2bfloat16(b - __bfloat162float(bh));
    __nv_bfloat162 ph; ph.x = ah; ph.y = bh;
    __nv_bfloat162 pl; pl.x = al; pl.y = bl;
    *(__nv_bfloat162*)(th + off) = ph;
    *(__nv_bfloat162*)(tl + off) = pl;
}

// Merged split-precision K=128 pass: C += Ah*Bh + Ah*Bl + Al*Bh.
// AT/BT: operand stored transposed ([k][m]/[k][n]) -> trans ldmatrix.
template<int AT, int BT>
__device__ __forceinline__ void gemm_triple(uint32_t aH, uint32_t aL,
                                            uint32_t bH, uint32_t bL,
                                            int m0, int n0, int lane, float c[2][4][4]) {
    #pragma unroll
    for (int ks = 0; ks < 8; ks++) {
        const int k0 = ks * 16;
        uint32_t ah[2][4], al[2][4];
        #pragma unroll
        for (int mt = 0; mt < 2; mt++) {
            uint32_t off;
            if (AT) {
                int krow = k0 + (lane & 7) + ((lane & 16) >> 1);
                int mcol = m0 + mt * 16 + (lane & 8);
                off = (uint32_t)((krow * LDA + mcol) * 2);
                ldsm4_t(ah[mt], aH + off);
                ldsm4_t(al[mt], aL + off);
            } else {
                int arow = m0 + mt * 16 + (lane & 15);
                int acol = k0 + ((lane >> 4) << 3);
                off = (uint32_t)((arow * LDA + acol) * 2);
                ldsm4(ah[mt], aH + off);
                ldsm4(al[mt], aL + off);
            }
        }
        uint32_t bh[4][2], bl[4][2];
        #pragma unroll
        for (int nb = 0; nb < 2; nb++) {
            uint32_t r[4], s[4], off;
            if (BT) {
                int krow = k0 + (lane & 7) + (lane & 8);
                int ncol = n0 + nb * 16 + ((lane & 16) >> 1);
                off = (uint32_t)((krow * LDA + ncol) * 2);
                ldsm4_t(r, bH + off);
                ldsm4_t(s, bL + off);
            } else {
                int nrow = n0 + nb * 16 + (lane & 7) + ((lane & 16) >> 1);
                int kcol = k0 + (lane & 8);
                off = (uint32_t)((nrow * LDA + kcol) * 2);
                ldsm4(r, bH + off);
                ldsm4(s, bL + off);
            }
            bh[2 * nb][0] = r[0];     bh[2 * nb][1] = r[1];
            bh[2 * nb + 1][0] = r[2]; bh[2 * nb + 1][1] = r[3];
            bl[2 * nb][0] = s[0];     bl[2 * nb][1] = s[1];
            bl[2 * nb + 1][0] = s[2]; bl[2 * nb + 1][1] = s[3];
        }
        #pragma unroll
        for (int mt = 0; mt < 2; mt++)
            #pragma unroll
            for (int nt = 0; nt < 4; nt++) {
                mma16816(c[mt][nt], ah[mt], bh[nt]);
                mma16816(c[mt][nt], ah[mt], bl[nt]);
                mma16816(c[mt][nt], al[mt], bh[nt]);
            }
    }
}

// ---------------------------------------------------------------------------
// conv1x1 via HMMA: Y[oc,s] = W[oc,ic].X[ic,s] + bias. W fp32; X either fp32
// (xf) or pre-split bf16 hi/lo (xbh/xbl). Output fp32.
// grid (128 s-tiles, OC/128, B), block 512 (16 warps, 32x32 warp tiles).
// ---------------------------------------------------------------------------
__global__ void __launch_bounds__(512, 1)
conv1x1_mma_k(const float* __restrict__ xf,
              const __nv_bfloat16* __restrict__ xbh, const __nv_bfloat16* __restrict__ xbl,
              const float* __restrict__ w, const float* __restrict__ bias,
              float* __restrict__ y, int OCtot) {
    extern __shared__ __align__(1024) char sm[];
    char* Wh = sm;              char* Wl = sm + TILEB;
    char* Xh = sm + 2 * TILEB;  char* Xl = sm + 3 * TILEB;
    __shared__ float biassm[128];

    const int tid = threadIdx.x;
    const int wid = tid >> 5, lane = tid & 31;
    const int s0  = blockIdx.x * 128;
    const int oc0 = blockIdx.y * 128;
    const int b   = blockIdx.z;

    if (tid < 128) biassm[tid] = bias[oc0 + tid];

    {   // stage W (convert fp32 -> hi/lo)
        const float4* wg = (const float4*)(w + (size_t)oc0 * 128);
        #pragma unroll
        for (int i = 0; i < 8; i++) {
            int idx4 = tid + i * 512;
            int r = idx4 >> 5, c4 = idx4 & 31;
            uint32_t o = (uint32_t)((r * LDA + 4 * c4) * 2);
            float4 v = wg[idx4];
            st_hilo_pair(Wh, Wl, o, v.x, v.y);
            st_hilo_pair(Wh, Wl, o + 4, v.z, v.w);
        }
    }
    if (xf) {   // stage X from fp32 (convert); tile row r = channel (stride HW)
        const float4* xg = (const float4*)(xf + (size_t)b * 128 * HW + s0);
        #pragma unroll
        for (int i = 0; i < 8; i++) {
            int idx4 = tid + i * 512;
            int r = idx4 >> 5, c4 = idx4 & 31;
            uint32_t o = (uint32_t)((r * LDA + 4 * c4) * 2);
            float4 xv = xg[r * (HW / 4) + c4];
            st_hilo_pair(Xh, Xl, o, xv.x, xv.y);
            st_hilo_pair(Xh, Xl, o + 4, xv.z, xv.w);
        }
    } else {    // stage X from pre-split bf16 (pure 16B copies); row stride = HW
        const uint4* hg = (const uint4*)(xbh + (size_t)b * 128 * HW + s0);
        const uint4* lg = (const uint4*)(xbl + (size_t)b * 128 * HW + s0);
        #pragma unroll
        for (int i = 0; i < 4; i++) {
            int idx = tid + i * 512;              // 2048 uint4 per tile
            int r = idx >> 4, c8 = idx & 15;
            uint32_t o = (uint32_t)(r * LDA * 2 + c8 * 16);
            *(uint4*)(Xh + o) = hg[r * (HW / 8) + c8];
            *(uint4*)(Xl + o) = lg[r * (HW / 8) + c8];
        }
    }
    __syncthreads();

    const int m0 = (wid & 3) * 32, n0 = (wid >> 2) * 32;
    float c[2][4][4];
    #pragma unroll
    for (int mt = 0; mt < 2; mt++)
        #pragma unroll
        for (int nt = 0; nt < 4; nt++)
            #pragma unroll
            for (int e = 0; e < 4; e++) c[mt][nt][e] = 0.f;

    gemm_triple<0, 1>(smem_u32(Wh), smem_u32(Wl), smem_u32(Xh), smem_u32(Xl),
                      m0, n0, lane, c);
    __syncthreads();   // X reads done -> reuse as fp32 stage

    float* stage = (float*)Xh;   // [128][132]
    const int g = lane >> 2, tg = lane & 3;
    #pragma unroll
    for (int mt = 0; mt < 2; mt++) {
        int r0 = m0 + mt * 16 + g, r1 = r0 + 8;
        float b0 = biassm[r0], b1 = biassm[r1];
        #pragma unroll
        for (int nt = 0; nt < 4; nt++) {
            int col = n0 + nt * 8 + 2 * tg;
            float2 p0; p0.x = c[mt][nt][0] + b0; p0.y = c[mt][nt][1] + b0;
            *(float2*)&stage[r0 * 132 + col] = p0;
            float2 p1; p1.x = c[mt][nt][2] + b1; p1.y = c[mt][nt][3] + b1;
            *(float2*)&stage[r1 * 132 + col] = p1;
        }
    }
    __syncthreads();
    float* yb = y + ((size_t)b * OCtot + oc0) * HW + s0;
    #pragma unroll
    for (int i = 0; i < 16; i++) {
        int idx = tid + i * 512;
        int row = idx >> 6, c2 = (idx & 63) * 2;
        *(float2*)&yb[(size_t)row * HW + c2] = *(float2*)&stage[row * 132 + c2];
    }
}

// ---------------------------------------------------------------------------
// depthwise 3x3, pad 1; fp32 in, hi/lo bf16 out. grid (4, B*384), block 256.
// ---------------------------------------------------------------------------
__global__ void dw3x3_k(const float* __restrict__ in, const float* __restrict__ w,
                        const float* __restrict__ bias,
                        __nv_bfloat16* __restrict__ oh, __nv_bfloat16* __restrict__ ol) {
    __shared__ float smd[34 * 128];
    const int tid = threadIdx.x;
    const int bc  = blockIdx.y;
    const int c   = bc % 384;
    const int h0  = blockIdx.x * 32;

    const float* src = in + (size_t)bc * HW;
    for (int idx = tid; idx < 34 * 128; idx += 256) {
        int r = idx >> 7, col = idx & 127;
        int h = h0 - 1 + r;
        smd[idx] = (h >= 0 && h < 128) ? src[h * 128 + col] : 0.f;
    }
    float wv[9];
    #pragma unroll
    for (int i = 0; i < 9; i++) wv[i] = w[c * 9 + i];
    const float bi = bias[c];
    __syncthreads();

    __nv_bfloat16* dh = oh + (size_t)bc * HW + h0 * 128;
    __nv_bfloat16* dl = ol + (size_t)bc * HW + h0 * 128;
    for (int idx = tid; idx < 32 * 64; idx += 256) {   // 2 cols per thread
        int r = idx >> 6, col = (idx & 63) * 2;
        float a0 = bi, a1 = bi;
        #pragma unroll
        for (int dy = 0; dy < 3; dy++) {
            #pragma unroll
            for (int dx = 0; dx < 3; dx++) {
                int c0 = col + dx - 1, c1 = c0 + 1;
                float wgt = wv[dy * 3 + dx];
                if (c0 >= 0) a0 = fmaf(wgt, smd[(r + dy) * 128 + c0], a0);
                if (c1 < 128) a1 = fmaf(wgt, smd[(r + dy) * 128 + c1], a1);
            }
        }
        __nv_bfloat16 h0b = __float2bfloat16(a0), h1b = __float2bfloat16(a1);
        __nv_bfloat162 ph; ph.x = h0b; ph.y = h1b;
        __nv_bfloat162 pl;
        pl.x = __float2bfloat16(a0 - __bfloat162float(h0b));
        pl.y = __float2bfloat16(a1 - __bfloat162float(h1b));
        *(__nv_bfloat162*)&dh[r * 128 + col] = ph;
        *(__nv_bfloat162*)&dl[r * 128 + col] = pl;
    }
}

// ---------------------------------------------------------------------------
// Attention per (b,head,c); one CTA each (1024), block 512, HMMA triple.
// Staging = pure bf16 copies from pre-split hi/lo planes (natural [i][w]).
// NOTE: tile rows here are CONTIGUOUS spatial rows (stride 128 elems = 16 uint4),
// unlike the conv kernel where rows are channels (stride HW).
//   GEMM1: Lt[k][j] = sum_i K[i][k]*Q[i][j]  (A,B trans loads)
//   scale rnk[k]*rqs[j] (temp folded), exp in regs, row sums shfl+smem,
//   P^T[k][j] hi/lo into K tiles. GEMM2: D2[i][k] = sum_j V[i][j]*P[j][k],
//   *sinv[k]; output written as hi/lo bf16 planes for proj.
// ---------------------------------------------------------------------------
__global__ void __launch_bounds__(512, 1)
attn_mma_k(const __nv_bfloat16* __restrict__ qh_g, const __nv_bfloat16* __restrict__ ql_g,
           const float* __restrict__ temp,
           __nv_bfloat16* __restrict__ oh, __nv_bfloat16* __restrict__ ol) {
    extern __shared__ __align__(1024) char sm[];
    char* Qh = sm;              char* Ql = sm + TILEB;
    char* Kh = sm + 2 * TILEB;  char* Kl = sm + 3 * TILEB;
    char* Vh = sm + 4 * TILEB;  char* Vl = sm + 5 * TILEB;
    __shared__ float rqs[128], rnk[128], sinv[128];
    __shared__ float psum[4][128], rowsum[4][128];

    const int tid = threadIdx.x;
    const int wid = tid >> 5, lane = tid & 31;
    const int cid = blockIdx.x;
    const int qc  = cid & 127;
    const int b   = cid >> 7;
    const int hd  = qc >> 5;

    const size_t base = ((size_t)b * 384 + qc) * HW;
    const uint4* qhg = (const uint4*)(qh_g + base);
    const uint4* qlg = (const uint4*)(ql_g + base);

    #pragma unroll
    for (int i = 0; i < 4; i++) {
        int idx = tid + i * 512;             // 2048 uint4 per tile
        int r = idx >> 4, c8 = idx & 15;
        uint32_t o = (uint32_t)(r * LDA * 2 + c8 * 16);
        int gi = r * 16 + c8;                // contiguous [128][128] tile: 16 uint4/row
        *(uint4*)(Qh + o) = qhg[gi];
        *(uint4*)(Ql + o) = qlg[gi];
        *(uint4*)(Kh + o) = qhg[gi + 128 * (HW / 8)];
        *(uint4*)(Kl + o) = qlg[gi + 128 * (HW / 8)];
        *(uint4*)(Vh + o) = qhg[gi + 256 * (HW / 8)];
        *(uint4*)(Vl + o) = qlg[gi + 256 * (HW / 8)];
    }
    __syncthreads();

    // Column L2 norms over i, 4 groups of 128 threads
    {
        int col = tid & 127, gq = tid >> 7;
        const char* bh = (gq < 2) ? Qh : Kh;
        const char* bl = (gq < 2) ? Ql : Kl;
        int i0 = (gq & 1) * 64;
        float s = 0.f;
        #pragma unroll 8
        for (int i = 0; i < 64; i++) {
            uint32_t o = (uint32_t)(((i0 + i) * LDA + col) * 2);
            float xv = bf2f(bh + o) + bf2f(bl + o);
            s = fmaf(xv, xv, s);
        }
        psum[gq][col] = s;
    }
    __syncthreads();
    {
        const float tp = temp[hd];
        if (tid < 128)
            rqs[tid] = tp / fmaxf(sqrtf(psum[0][tid] + psum[1][tid]), 1e-12f);
        else if (tid < 256) {
            int c2 = tid - 128;
            rnk[c2] = 1.f / fmaxf(sqrtf(psum[2][c2] + psum[3][c2]), 1e-12f);
        }
    }
    __syncthreads();

    const int m0 = (wid & 3) * 32, n0 = (wid >> 2) * 32;
    float c[2][4][4];
    #pragma unroll
    for (int mt = 0; mt < 2; mt++)
        #pragma unroll
        for (int nt = 0; nt < 4; nt++)
            #pragma unroll
            for (int e = 0; e < 4; e++) c[mt][nt][e] = 0.f;

    gemm_triple<1, 1>(smem_u32(Kh), smem_u32(Kl), smem_u32(Qh), smem_u32(Ql),
                      m0, n0, lane, c);

    // scale + exp in regs, row-partial sums
    const int g = lane >> 2, tg = lane & 3;
    float rs[4] = {0.f, 0.f, 0.f, 0.f};
    #pragma unroll
    for (int mt = 0; mt < 2; mt++) {
        int r0 = m0 + mt * 16 + g, r1 = r0 + 8;
        float k0s = rnk[r0], k1s = rnk[r1];
        #pragma unroll
        for (int nt = 0; nt < 4; nt++) {
            int j0 = n0 + nt * 8 + 2 * tg;
            float q0 = rqs[j0], q1 = rqs[j0 + 1];
            float e0 = __expf(c[mt][nt][0] * k0s * q0);
            float e1 = __expf(c[mt][nt][1] * k0s * q1);
            float e2 = __expf(c[mt][nt][2] * k1s * q0);
            float e3 = __expf(c[mt][nt][3] * k1s * q1);
            c[mt][nt][0] = e0; c[mt][nt][1] = e1;
            c[mt][nt][2] = e2; c[mt][nt][3] = e3;
            rs[2 * mt] += e0 + e1;
            rs[2 * mt + 1] += e2 + e3;
        }
    }
    __syncthreads();   // GEMM1 reads done

    #pragma unroll
    for (int mt = 0; mt < 2; mt++) {
        int r0 = m0 + mt * 16 + g, r1 = r0 + 8;
        #pragma unroll
        for (int nt = 0; nt < 4; nt++) {
            int j0 = n0 + nt * 8 + 2 * tg;
            st_hilo_pair(Kh, Kl, (uint32_t)((r0 * LDA + j0) * 2), c[mt][nt][0], c[mt][nt][1]);
            st_hilo_pair(Kh, Kl, (uint32_t)((r1 * LDA + j0) * 2), c[mt][nt][2], c[mt][nt][3]);
        }
    }
    #pragma unroll
    for (int i = 0; i < 4; i++) {
        rs[i] += __shfl_xor_sync(0xFFFFFFFFu, rs[i], 1);
        rs[i] += __shfl_xor_sync(0xFFFFFFFFu, rs[i], 2);
    }
    if (tg == 0) {
        int grp = wid >> 2;
        rowsum[grp][m0 + g]      = rs[0];
        rowsum[grp][m0 + 8 + g]  = rs[1];
        rowsum[grp][m0 + 16 + g] = rs[2];
        rowsum[grp][m0 + 24 + g] = rs[3];
    }
    __syncthreads();
    if (tid < 128)
        sinv[tid] = 1.f / (rowsum[0][tid] + rowsum[1][tid] + rowsum[2][tid] + rowsum[3][tid]);

    // GEMM2: A = V natural, B = Pt natural
    #pragma unroll
    for (int mt = 0; mt < 2; mt++)
        #pragma unroll
        for (int nt = 0; nt < 4; nt++)
            #pragma unroll
            for (int e = 0; e < 4; e++) c[mt][nt][e] = 0.f;
    gemm_triple<0, 0>(smem_u32(Vh), smem_u32(Vl), smem_u32(Kh), smem_u32(Kl),
                      m0, n0, lane, c);
    __syncthreads();   // sinv visible; Q tiles free

    float* stage = (float*)Qh;   // [128][132]
    #pragma unroll
    for (int mt = 0; mt < 2; mt++) {
        int r0 = m0 + mt * 16 + g, r1 = r0 + 8;
        #pragma unroll
        for (int nt = 0; nt < 4; nt++) {
            int col = n0 + nt * 8 + 2 * tg;
            float s0 = sinv[col], s1 = sinv[col + 1];
            float2 p0; p0.x = c[mt][nt][0] * s0; p0.y = c[mt][nt][1] * s1;
            *(float2*)&stage[r0 * 132 + col] = p0;
            float2 p1; p1.x = c[mt][nt][2] * s0; p1.y = c[mt][nt][3] * s1;
            *(float2*)&stage[r1 * 132 + col] = p1;
        }
    }
    __syncthreads();
    const size_t ob = ((size_t)b * 128 + qc) * HW;
    #pragma unroll
    for (int i = 0; i < 16; i++) {
        int idx = tid + i * 512;
        int row = idx >> 6, c2 = (idx & 63) * 2;
        float2 v = *(float2*)&stage[row * 132 + c2];
        __nv_bfloat16 h0b = __float2bfloat16(v.x), h1b = __float2bfloat16(v.y);
        __nv_bfloat162 ph; ph.x = h0b; ph.y = h1b;
        __nv_bfloat162 pl;
        pl.x = __float2bfloat16(v.x - __bfloat162float(h0b));
        pl.y = __float2bfloat16(v.y - __bfloat162float(h1b));
        *(__nv_bfloat162*)&oh[ob + row * 128 + c2] = ph;
        *(__nv_bfloat162*)&ol[ob + row * 128 + c2] = pl;
    }
}

// ---------------------------------------------------------------------------
extern "C" void kernel_launch(void* const* d_in, const int* in_sizes, int n_in,
                              void* d_out, int out_size) {
    const float* x      = (const float*)d_in[0];
    const float* qkv_w  = (const float*)d_in[1];
    const float* qkv_b  = (const float*)d_in[2];
    const float* dw_w   = (const float*)d_in[3];
    const float* dw_b   = (const float*)d_in[4];
    const float* proj_w = (const float*)d_in[5];
    const float* proj_b = (const float*)d_in[6];
    const float* temp   = (const float*)d_in[7];
    float* out = (float*)d_out;

    void *p1, *p2h, *p2l, *p3h, *p3l;
    cudaGetSymbolAddress(&p1, g_qkv1);
    cudaGetSymbolAddress(&p2h, g_q2h);
    cudaGetSymbolAddress(&p2l, g_q2l);
    cudaGetSymbolAddress(&p3h, g_aoh);
    cudaGetSymbolAddress(&p3l, g_aol);
    float* qkv1 = (float*)p1;
    __nv_bfloat16* q2h = (__nv_bfloat16*)p2h;
    __nv_bfloat16* q2l = (__nv_bfloat16*)p2l;
    __nv_bfloat16* aoh = (__nv_bfloat16*)p3h;
    __nv_bfloat16* aol = (__nv_bfloat16*)p3l;

    const int conv_smem = 4 * TILEB;   // 139264
    const int attn_smem = 6 * TILEB;   // 208896
    cudaFuncSetAttribute(conv1x1_mma_k, cudaFuncAttributeMaxDynamicSharedMemorySize, conv_smem);
    cudaFuncSetAttribute(attn_mma_k,    cudaFuncAttributeMaxDynamicSharedMemorySize, attn_smem);

    // 1) qkv = conv1x1(x)  (fp32 in, fp32 out)
    conv1x1_mma_k<<<dim3(128, 3, NB), 512, conv_smem>>>(
        x, nullptr, nullptr, qkv_w, qkv_b, qkv1, 384);
    // 2) qkv = dwconv3x3(qkv)  (fp32 in, hi/lo bf16 out)
    dw3x3_k<<<dim3(4, NB * 384), 256>>>(qkv1, dw_w, dw_b, q2h, q2l);
    // 3) transposed attention (hi/lo in, hi/lo out)
    attn_mma_k<<<dim3(1024), 512, attn_smem>>>(q2h, q2l, temp, aoh, aol);
    // 4) out = conv1x1(attn_out)  (hi/lo in, fp32 out)
    conv1x1_mma_k<<<dim3(128, 1, NB), 512, conv_smem>>>(
        nullptr, aoh, aol, proj_w, proj_b, out, 128);
}

// round 12
// speedup vs baseline: 1.6581x; 1.0475x over previous
#include <cuda_runtime.h>
#include <cuda_bf16.h>
#include <math.h>
#include <stdint.h>

#define HW 16384      // 128*128
#define NB 8          // batch
#define LDA 136       // padded bf16 row stride (272B -> conflict-free ldmatrix rows)
#define TILEB (128 * LDA * 2)   // 34816 bytes per 128x128 bf16 tile

// Scratch (device globals; allocation inside kernel_launch is forbidden)
__device__ __nv_bfloat16 g_xh[16777216];      // x split hi
__device__ __nv_bfloat16 g_xl[16777216];      // x split lo
__device__ float g_qkv1[50331648];            // [8][384][16384] conv1x1 out (fp32)
__device__ __nv_bfloat16 g_q2h[50331648];     // dwconv out hi
__device__ __nv_bfloat16 g_q2l[50331648];     // dwconv out lo
__device__ __nv_bfloat16 g_aoh[16777216];     // attn out hi
__device__ __nv_bfloat16 g_aol[16777216];     // attn out lo

// ============================ helpers ==================================
__device__ __forceinline__ uint32_t smem_u32(const void* p) {
    uint32_t a;
    asm("{ .reg .u64 t; cvta.to.shared.u64 t, %1; cvt.u32.u64 %0, t; }" : "=r"(a) : "l"(p));
    return a;
}
__device__ __forceinline__ void ldsm4(uint32_t* r, uint32_t addr) {
    asm volatile("ldmatrix.sync.aligned.m8n8.x4.shared.b16 {%0,%1,%2,%3}, [%4];"
                 : "=r"(r[0]), "=r"(r[1]), "=r"(r[2]), "=r"(r[3]) : "r"(addr));
}
__device__ __forceinline__ void ldsm4_t(uint32_t* r, uint32_t addr) {
    asm volatile("ldmatrix.sync.aligned.m8n8.x4.trans.shared.b16 {%0,%1,%2,%3}, [%4];"
                 : "=r"(r[0]), "=r"(r[1]), "=r"(r[2]), "=r"(r[3]) : "r"(addr));
}
__device__ __forceinline__ void mma16816(float* d, const uint32_t* a, const uint32_t* b) {
    asm volatile("mma.sync.aligned.m16n8k16.row.col.f32.bf16.bf16.f32 "
        "{%0,%1,%2,%3}, {%4,%5,%6,%7}, {%8,%9}, {%0,%1,%2,%3};"
        : "+f"(d[0]), "+f"(d[1]), "+f"(d[2]), "+f"(d[3])
        : "r"(a[0]), "r"(a[1]), "r"(a[2]), "r"(a[3]), "r"(b[0]), "r"(b[1]));
}
__device__ __forceinline__ float bf2f(const void* p) {
    return __bfloat162float(*(const __nv_bfloat16*)p);
}
__device__ __forceinline__ void st_hilo_pair(char* th, char* tl, uint32_t off, float a, float b) {
    __nv_bfloat16 ah = __float2bfloat16(a), bh = __float2bfloat16(b);
    __nv_bfloat16 al = __float2bfloat16(a - __bfloat162float(ah));
    __nv_bfloat16 bl = __float2bfloat16(b - __bfloat162float(bh));
    __nv_bfloat162 ph; ph.x = ah; ph.y = bh;
    __nv_bfloat162 pl; pl.x = al; pl.y = bl;
    *(__nv_bfloat162*)(th + off) = ph;
    *(__nv_bfloat162*)(tl + off) = pl;
}
__device__ __forceinline__ void cpa16(uint32_t dst, const void* src) {
    asm volatile("cp.async.cg.shared.global [%0], [%1], 16;" :: "r"(dst), "l"(src));
}
#define CPA_COMMIT() asm volatile("cp.async.commit_group;" ::: "memory")
#define CPA_WAIT(n)  asm volatile("cp.async.wait_group %0;" :: "n"(n) : "memory")

// Merged split-precision K=128 pass: C += Ah*Bh + Ah*Bl + Al*Bh.
// Pass-major MMA order: 8 independent MMAs between accumulator reuses.
template<int AT, int BT>
__device__ __forceinline__ void gemm_triple(uint32_t aH, uint32_t aL,
                                            uint32_t bH, uint32_t bL,
                                            int m0, int n0, int lane, float c[2][4][4]) {
    #pragma unroll
    for (int ks = 0; ks < 8; ks++) {
        const int k0 = ks * 16;
        uint32_t ah[2][4], al[2][4];
        #pragma unroll
        for (int mt = 0; mt < 2; mt++) {
            uint32_t off;
            if (AT) {
                int krow = k0 + (lane & 7) + ((lane & 16) >> 1);
                int mcol = m0 + mt * 16 + (lane & 8);
                off = (uint32_t)((krow * LDA + mcol) * 2);
                ldsm4_t(ah[mt], aH + off);
                ldsm4_t(al[mt], aL + off);
            } else {
                int arow = m0 + mt * 16 + (lane & 15);
                int acol = k0 + ((lane >> 4) << 3);
                off = (uint32_t)((arow * LDA + acol) * 2);
                ldsm4(ah[mt], aH + off);
                ldsm4(al[mt], aL + off);
            }
        }
        uint32_t bh[4][2], bl[4][2];
        #pragma unroll
        for (int nb = 0; nb < 2; nb++) {
            uint32_t r[4], s[4], off;
            if (BT) {
                int krow = k0 + (lane & 7) + (lane & 8);
                int ncol = n0 + nb * 16 + ((lane & 16) >> 1);
                off = (uint32_t)((krow * LDA + ncol) * 2);
                ldsm4_t(r, bH + off);
                ldsm4_t(s, bL + off);
            } else {
                int nrow = n0 + nb * 16 + (lane & 7) + ((lane & 16) >> 1);
                int kcol = k0 + (lane & 8);
                off = (uint32_t)((nrow * LDA + kcol) * 2);
                ldsm4(r, bH + off);
                ldsm4(s, bL + off);
            }
            bh[2 * nb][0] = r[0];     bh[2 * nb][1] = r[1];
            bh[2 * nb + 1][0] = r[2]; bh[2 * nb + 1][1] = r[3];
            bl[2 * nb][0] = s[0];     bl[2 * nb][1] = s[1];
            bl[2 * nb + 1][0] = s[2]; bl[2 * nb + 1][1] = s[3];
        }
        #pragma unroll
        for (int mt = 0; mt < 2; mt++)
            #pragma unroll
            for (int nt = 0; nt < 4; nt++)
                mma16816(c[mt][nt], ah[mt], bh[nt]);
        #pragma unroll
        for (int mt = 0; mt < 2; mt++)
            #pragma unroll
            for (int nt = 0; nt < 4; nt++)
                mma16816(c[mt][nt], ah[mt], bl[nt]);
        #pragma unroll
        for (int mt = 0; mt < 2; mt++)
            #pragma unroll
            for (int nt = 0; nt < 4; nt++)
                mma16816(c[mt][nt], al[mt], bh[nt]);
    }
}

// ---------------------------------------------------------------------------
// split fp32 -> hi/lo bf16 planes. grid 4096, block 512, 8 floats/thread.
// ---------------------------------------------------------------------------
__global__ void __launch_bounds__(512, 2)
splitx_k(const float* __restrict__ x, __nv_bfloat16* __restrict__ xh,
         __nv_bfloat16* __restrict__ xl) {
    size_t i = ((size_t)blockIdx.x * 512 + threadIdx.x) * 8;
    float4 a = *(const float4*)(x + i);
    float4 b = *(const float4*)(x + i + 4);
    float v[8] = {a.x, a.y, a.z, a.w, b.x, b.y, b.z, b.w};
    uint32_t uh[4], ul[4];
    #pragma unroll
    for (int k = 0; k < 4; k++) {
        __nv_bfloat16 h0 = __float2bfloat16(v[2 * k]);
        __nv_bfloat16 h1 = __float2bfloat16(v[2 * k + 1]);
        __nv_bfloat162 ph; ph.x = h0; ph.y = h1;
        __nv_bfloat162 pl;
        pl.x = __float2bfloat16(v[2 * k] - __bfloat162float(h0));
        pl.y = __float2bfloat16(v[2 * k + 1] - __bfloat162float(h1));
        uh[k] = *(uint32_t*)&ph;
        ul[k] = *(uint32_t*)&pl;
    }
    *(uint4*)(xh + i) = *(uint4*)uh;
    *(uint4*)(xl + i) = *(uint4*)ul;
}

// ---------------------------------------------------------------------------
// conv1x1 via HMMA, 4 spatial tiles per CTA, cp.async double-buffered X.
// Y[oc,s] = W[oc,ic].X[ic,s] + bias; X given as hi/lo bf16 planes.
// grid (32 s-groups, OC/128, B), block 512 (16 warps, 32x32 warp tiles).
// smem: Wh,Wl + Xbuf0(h,l) + Xbuf1(h,l) = 6 tiles = 208896B.
// ---------------------------------------------------------------------------
__global__ void __launch_bounds__(512, 1)
conv1x1_mma_k(const __nv_bfloat16* __restrict__ xbh, const __nv_bfloat16* __restrict__ xbl,
              const float* __restrict__ w, const float* __restrict__ bias,
              float* __restrict__ y, int OCtot) {
    extern __shared__ __align__(1024) char sm[];
    char* Wh = sm;
    char* Wl = sm + TILEB;
    __shared__ float biassm[128];

    const int tid = threadIdx.x;
    const int wid = tid >> 5, lane = tid & 31;
    const int sg  = blockIdx.x;          // 512-wide spatial group
    const int oc0 = blockIdx.y * 128;
    const int b   = blockIdx.z;
    const uint32_t smb = smem_u32(sm);

    if (tid < 128) biassm[tid] = bias[oc0 + tid];

    {   // stage W once (convert fp32 -> hi/lo)
        const float4* wg = (const float4*)(w + (size_t)oc0 * 128);
        #pragma unroll
        for (int i = 0; i < 8; i++) {
            int idx4 = tid + i * 512;
            int r = idx4 >> 5, c4 = idx4 & 31;
            uint32_t o = (uint32_t)((r * LDA + 4 * c4) * 2);
            float4 v = wg[idx4];
            st_hilo_pair(Wh, Wl, o, v.x, v.y);
            st_hilo_pair(Wh, Wl, o + 4, v.z, v.w);
        }
    }

    const size_t xbase = (size_t)b * 128 * HW;
    const int r_ = tid >> 4, c8_ = tid & 15;   // reused pattern pieces

    // issue cp.async for tile t into buffer (t&1)
    auto issue_tile = [&](int t) {
        int bsel = t & 1;
        uint32_t bhs = smb + (uint32_t)(2 + 2 * bsel) * TILEB;
        uint32_t bls = bhs + TILEB;
        int s0 = sg * 512 + t * 128;
        const __nv_bfloat16* ph = xbh + xbase + s0;
        const __nv_bfloat16* pl = xbl + xbase + s0;
        #pragma unroll
        for (int i = 0; i < 4; i++) {
            int idx = tid + i * 512;
            int r = idx >> 4, c8 = idx & 15;
            uint32_t so = (uint32_t)(r * LDA * 2 + c8 * 16);
            size_t go = (size_t)r * HW + c8 * 8;
            cpa16(bhs + so, ph + go);
            cpa16(bls + so, pl + go);
        }
        CPA_COMMIT();
    };

    issue_tile(0);

    const int m0 = (wid & 3) * 32, n0 = (wid >> 2) * 32;
    const int g = lane >> 2, tg = lane & 3;
    const uint32_t aWh = smb, aWl = smb + TILEB;

    #pragma unroll
    for (int t = 0; t < 4; t++) {
        if (t < 3) issue_tile(t + 1);
        if (t < 3) { CPA_WAIT(1); } else { CPA_WAIT(0); }
        __syncthreads();

        float c[2][4][4];
        #pragma unroll
        for (int mt = 0; mt < 2; mt++)
            #pragma unroll
            for (int nt = 0; nt < 4; nt++)
                #pragma unroll
                for (int e = 0; e < 4; e++) c[mt][nt][e] = 0.f;

        uint32_t bhs = smb + (uint32_t)(2 + 2 * (t & 1)) * TILEB;
        gemm_triple<0, 1>(aWh, aWl, bhs, bhs + TILEB, m0, n0, lane, c);
        __syncthreads();   // X buffer reads done -> overlay as fp32 stage

        float* stage = (float*)(sm + (size_t)(2 + 2 * (t & 1)) * TILEB);  // [128][132]
        #pragma unroll
        for (int mt = 0; mt < 2; mt++) {
            int r0 = m0 + mt * 16 + g, r1 = r0 + 8;
            float b0 = biassm[r0], b1 = biassm[r1];
            #pragma unroll
            for (int nt = 0; nt < 4; nt++) {
                int col = n0 + nt * 8 + 2 * tg;
                float2 p0; p0.x = c[mt][nt][0] + b0; p0.y = c[mt][nt][1] + b0;
                *(float2*)&stage[r0 * 132 + col] = p0;
                float2 p1; p1.x = c[mt][nt][2] + b1; p1.y = c[mt][nt][3] + b1;
                *(float2*)&stage[r1 * 132 + col] = p1;
            }
        }
        __syncthreads();
        int s0 = sg * 512 + t * 128;
        float* yb = y + ((size_t)b * OCtot + oc0) * HW + s0;
        #pragma unroll
        for (int i = 0; i < 16; i++) {
            int idx = tid + i * 512;
            int row = idx >> 6, c2 = (idx & 63) * 2;
            *(float2*)&yb[(size_t)row * HW + c2] = *(float2*)&stage[row * 132 + c2];
        }
        __syncthreads();   // stage reads done before next cp.async reuses buffer
    }
    (void)r_; (void)c8_;
}

// ---------------------------------------------------------------------------
// depthwise 3x3, pad 1; fp32 in, hi/lo bf16 out. grid (4, B*384), block 256.
// ---------------------------------------------------------------------------
__global__ void dw3x3_k(const float* __restrict__ in, const float* __restrict__ w,
                        const float* __restrict__ bias,
                        __nv_bfloat16* __restrict__ oh, __nv_bfloat16* __restrict__ ol) {
    __shared__ float smd[34 * 128];
    const int tid = threadIdx.x;
    const int bc  = blockIdx.y;
    const int c   = bc % 384;
    const int h0  = blockIdx.x * 32;

    const float* src = in + (size_t)bc * HW;
    for (int idx = tid; idx < 34 * 128; idx += 256) {
        int r = idx >> 7, col = idx & 127;
        int h = h0 - 1 + r;
        smd[idx] = (h >= 0 && h < 128) ? src[h * 128 + col] : 0.f;
    }
    float wv[9];
    #pragma unroll
    for (int i = 0; i < 9; i++) wv[i] = w[c * 9 + i];
    const float bi = bias[c];
    __syncthreads();

    __nv_bfloat16* dh = oh + (size_t)bc * HW + h0 * 128;
    __nv_bfloat16* dl = ol + (size_t)bc * HW + h0 * 128;
    for (int idx = tid; idx < 32 * 64; idx += 256) {   // 2 cols per thread
        int r = idx >> 6, col = (idx & 63) * 2;
        float a0 = bi, a1 = bi;
        #pragma unroll
        for (int dy = 0; dy < 3; dy++) {
            #pragma unroll
            for (int dx = 0; dx < 3; dx++) {
                int c0 = col + dx - 1, c1 = c0 + 1;
                float wgt = wv[dy * 3 + dx];
                if (c0 >= 0) a0 = fmaf(wgt, smd[(r + dy) * 128 + c0], a0);
                if (c1 < 128) a1 = fmaf(wgt, smd[(r + dy) * 128 + c1], a1);
            }
        }
        __nv_bfloat16 h0b = __float2bfloat16(a0), h1b = __float2bfloat16(a1);
        __nv_bfloat162 ph; ph.x = h0b; ph.y = h1b;
        __nv_bfloat162 pl;
        pl.x = __float2bfloat16(a0 - __bfloat162float(h0b));
        pl.y = __float2bfloat16(a1 - __bfloat162float(h1b));
        *(__nv_bfloat162*)&dh[r * 128 + col] = ph;
        *(__nv_bfloat162*)&dl[r * 128 + col] = pl;
    }
}

// ---------------------------------------------------------------------------
// Attention per (b,head,c); one CTA each (1024), block 512, HMMA triple.
// cp.async staging: Q,K in group A (needed first), V in group B (waited only
// before GEMM2 -> latency hidden behind norms + GEMM1 + exp).
// ---------------------------------------------------------------------------
__global__ void __launch_bounds__(512, 1)
attn_mma_k(const __nv_bfloat16* __restrict__ qh_g, const __nv_bfloat16* __restrict__ ql_g,
           const float* __restrict__ temp,
           __nv_bfloat16* __restrict__ oh, __nv_bfloat16* __restrict__ ol) {
    extern __shared__ __align__(1024) char sm[];
    char* Qh = sm;              char* Ql = sm + TILEB;
    char* Kh = sm + 2 * TILEB;  char* Kl = sm + 3 * TILEB;
    __shared__ float rqs[128], rnk[128], sinv[128];
    __shared__ float psum[4][128], rowsum[4][128];

    const int tid = threadIdx.x;
    const int wid = tid >> 5, lane = tid & 31;
    const int cid = blockIdx.x;
    const int qc  = cid & 127;
    const int b   = cid >> 7;
    const int hd  = qc >> 5;
    const uint32_t smb = smem_u32(sm);

    const size_t base = ((size_t)b * 384 + qc) * HW;

    // group A: Q,K tiles
    #pragma unroll
    for (int i = 0; i < 4; i++) {
        int idx = tid + i * 512;
        int r = idx >> 4, c8 = idx & 15;
        uint32_t so = (uint32_t)(r * LDA * 2 + c8 * 16);
        size_t go = base + (size_t)r * 128 + c8 * 8;
        cpa16(smb + so, qh_g + go);                              // Qh
        cpa16(smb + TILEB + so, ql_g + go);                      // Ql
        cpa16(smb + 2 * TILEB + so, qh_g + go + 128 * HW);       // Kh
        cpa16(smb + 3 * TILEB + so, ql_g + go + 128 * HW);       // Kl
    }
    CPA_COMMIT();
    // group B: V tiles
    #pragma unroll
    for (int i = 0; i < 4; i++) {
        int idx = tid + i * 512;
        int r = idx >> 4, c8 = idx & 15;
        uint32_t so = (uint32_t)(r * LDA * 2 + c8 * 16);
        size_t go = base + (size_t)r * 128 + c8 * 8;
        cpa16(smb + 4 * TILEB + so, qh_g + go + 256 * HW);       // Vh
        cpa16(smb + 5 * TILEB + so, ql_g + go + 256 * HW);       // Vl
    }
    CPA_COMMIT();
    CPA_WAIT(1);         // Q,K complete; V still in flight
    __syncthreads();

    // Column L2 norms over i, 4 groups of 128 threads
    {
        int col = tid & 127, gq = tid >> 7;
        const char* bh = (gq < 2) ? Qh : Kh;
        const char* bl = (gq < 2) ? Ql : Kl;
        int i0 = (gq & 1) * 64;
        float s = 0.f;
        #pragma unroll 8
        for (int i = 0; i < 64; i++) {
            uint32_t o = (uint32_t)(((i0 + i) * LDA + col) * 2);
            float xv = bf2f(bh + o) + bf2f(bl + o);
            s = fmaf(xv, xv, s);
        }
        psum[gq][col] = s;
    }
    __syncthreads();
    {
        const float tp = temp[hd];
        if (tid < 128)
            rqs[tid] = tp / fmaxf(sqrtf(psum[0][tid] + psum[1][tid]), 1e-12f);
        else if (tid < 256) {
            int c2 = tid - 128;
            rnk[c2] = 1.f / fmaxf(sqrtf(psum[2][c2] + psum[3][c2]), 1e-12f);
        }
    }
    __syncthreads();

    const int m0 = (wid & 3) * 32, n0 = (wid >> 2) * 32;
    float c[2][4][4];
    #pragma unroll
    for (int mt = 0; mt < 2; mt++)
        #pragma unroll
        for (int nt = 0; nt < 4; nt++)
            #pragma unroll
            for (int e = 0; e < 4; e++) c[mt][nt][e] = 0.f;

    gemm_triple<1, 1>(smb + 2 * TILEB, smb + 3 * TILEB, smb, smb + TILEB,
                      m0, n0, lane, c);

    // scale + exp in regs, row-partial sums
    const int g = lane >> 2, tg = lane & 3;
    float rs[4] = {0.f, 0.f, 0.f, 0.f};
    #pragma unroll
    for (int mt = 0; mt < 2; mt++) {
        int r0 = m0 + mt * 16 + g, r1 = r0 + 8;
        float k0s = rnk[r0], k1s = rnk[r1];
        #pragma unroll
        for (int nt = 0; nt < 4; nt++) {
            int j0 = n0 + nt * 8 + 2 * tg;
            float q0 = rqs[j0], q1 = rqs[j0 + 1];
            float e0 = __expf(c[mt][nt][0] * k0s * q0);
            float e1 = __expf(c[mt][nt][1] * k0s * q1);
            float e2 = __expf(c[mt][nt][2] * k1s * q0);
            float e3 = __expf(c[mt][nt][3] * k1s * q1);
            c[mt][nt][0] = e0; c[mt][nt][1] = e1;
            c[mt][nt][2] = e2; c[mt][nt][3] = e3;
            rs[2 * mt] += e0 + e1;
            rs[2 * mt + 1] += e2 + e3;
        }
    }
    CPA_WAIT(0);         // V complete (hidden behind norms+GEMM1+exp)
    __syncthreads();     // GEMM1 reads done; V visible to all threads

    #pragma unroll
    for (int mt = 0; mt < 2; mt++) {
        int r0 = m0 + mt * 16 + g, r1 = r0 + 8;
        #pragma unroll
        for (int nt = 0; nt < 4; nt++) {
            int j0 = n0 + nt * 8 + 2 * tg;
            st_hilo_pair(Kh, Kl, (uint32_t)((r0 * LDA + j0) * 2), c[mt][nt][0], c[mt][nt][1]);
            st_hilo_pair(Kh, Kl, (uint32_t)((r1 * LDA + j0) * 2), c[mt][nt][2], c[mt][nt][3]);
        }
    }
    #pragma unroll
    for (int i = 0; i < 4; i++) {
        rs[i] += __shfl_xor_sync(0xFFFFFFFFu, rs[i], 1);
        rs[i] += __shfl_xor_sync(0xFFFFFFFFu, rs[i], 2);
    }
    if (tg == 0) {
        int grp = wid >> 2;
        rowsum[grp][m0 + g]      = rs[0];
        rowsum[grp][m0 + 8 + g]  = rs[1];
        rowsum[grp][m0 + 16 + g] = rs[2];
        rowsum[grp][m0 + 24 + g] = rs[3];
    }
    __syncthreads();
    if (tid < 128)
        sinv[tid] = 1.f / (rowsum[0][tid] + rowsum[1][tid] + rowsum[2][tid] + rowsum[3][tid]);

    // GEMM2: A = V natural, B = Pt natural
    #pragma unroll
    for (int mt = 0; mt < 2; mt++)
        #pragma unroll
        for (int nt = 0; nt < 4; nt++)
            #pragma unroll
            for (int e = 0; e < 4; e++) c[mt][nt][e] = 0.f;
    gemm_triple<0, 0>(smb + 4 * TILEB, smb + 5 * TILEB, smb + 2 * TILEB, smb + 3 * TILEB,
                      m0, n0, lane, c);
    __syncthreads();   // sinv visible; Q tiles free

    float* stage = (float*)Qh;   // [128][132]
    #pragma unroll
    for (int mt = 0; mt < 2; mt++) {
        int r0 = m0 + mt * 16 + g, r1 = r0 + 8;
        #pragma unroll
        for (int nt = 0; nt < 4; nt++) {
            int col = n0 + nt * 8 + 2 * tg;
            float s0 = sinv[col], s1 = sinv[col + 1];
            float2 p0; p0.x = c[mt][nt][0] * s0; p0.y = c[mt][nt][1] * s1;
            *(float2*)&stage[r0 * 132 + col] = p0;
            float2 p1; p1.x = c[mt][nt][2] * s0; p1.y = c[mt][nt][3] * s1;
            *(float2*)&stage[r1 * 132 + col] = p1;
        }
    }
    __syncthreads();
    const size_t ob = ((size_t)b * 128 + qc) * HW;
    #pragma unroll
    for (int i = 0; i < 16; i++) {
        int idx = tid + i * 512;
        int row = idx >> 6, c2 = (idx & 63) * 2;
        float2 v = *(float2*)&stage[row * 132 + c2];
        __nv_bfloat16 h0b = __float2bfloat16(v.x), h1b = __float2bfloat16(v.y);
        __nv_bfloat162 ph; ph.x = h0b; ph.y = h1b;
        __nv_bfloat162 pl;
        pl.x = __float2bfloat16(v.x - __bfloat162float(h0b));
        pl.y = __float2bfloat16(v.y - __bfloat162float(h1b));
        *(__nv_bfloat162*)&oh[ob + row * 128 + c2] = ph;
        *(__nv_bfloat162*)&ol[ob + row * 128 + c2] = pl;
    }
}

// ---------------------------------------------------------------------------
extern "C" void kernel_launch(void* const* d_in, const int* in_sizes, int n_in,
                              void* d_out, int out_size) {
    const float* x      = (const float*)d_in[0];
    const float* qkv_w  = (const float*)d_in[1];
    const float* qkv_b  = (const float*)d_in[2];
    const float* dw_w   = (const float*)d_in[3];
    const float* dw_b   = (const float*)d_in[4];
    const float* proj_w = (const float*)d_in[5];
    const float* proj_b = (const float*)d_in[6];
    const float* temp   = (const float*)d_in[7];
    float* out = (float*)d_out;

    void *pxh, *pxl, *p1, *p2h, *p2l, *p3h, *p3l;
    cudaGetSymbolAddress(&pxh, g_xh);
    cudaGetSymbolAddress(&pxl, g_xl);
    cudaGetSymbolAddress(&p1, g_qkv1);
    cudaGetSymbolAddress(&p2h, g_q2h);
    cudaGetSymbolAddress(&p2l, g_q2l);
    cudaGetSymbolAddress(&p3h, g_aoh);
    cudaGetSymbolAddress(&p3l, g_aol);
    __nv_bfloat16* xh = (__nv_bfloat16*)pxh;
    __nv_bfloat16* xl = (__nv_bfloat16*)pxl;
    float* qkv1 = (float*)p1;
    __nv_bfloat16* q2h = (__nv_bfloat16*)p2h;
    __nv_bfloat16* q2l = (__nv_bfloat16*)p2l;
    __nv_bfloat16* aoh = (__nv_bfloat16*)p3h;
    __nv_bfloat16* aol = (__nv_bfloat16*)p3l;

    const int conv_smem = 6 * TILEB;   // 208896
    const int attn_smem = 6 * TILEB;   // 208896
    cudaFuncSetAttribute(conv1x1_mma_k, cudaFuncAttributeMaxDynamicSharedMemorySize, conv_smem);
    cudaFuncSetAttribute(attn_mma_k,    cudaFuncAttributeMaxDynamicSharedMemorySize, attn_smem);

    // 0) split x into hi/lo bf16 planes
    splitx_k<<<4096, 512>>>(x, xh, xl);
    // 1) qkv = conv1x1(x)  (hi/lo in, fp32 out), 4 tiles/CTA pipelined
    conv1x1_mma_k<<<dim3(32, 3, NB), 512, conv_smem>>>(xh, xl, qkv_w, qkv_b, qkv1, 384);
    // 2) qkv = dwconv3x3(qkv)  (fp32 in, hi/lo bf16 out)
    dw3x3_k<<<dim3(4, NB * 384), 256>>>(qkv1, dw_w, dw_b, q2h, q2l);
    // 3) transposed attention (hi/lo in, hi/lo out)
    attn_mma_k<<<dim3(1024), 512, attn_smem>>>(q2h, q2l, temp, aoh, aol);
    // 4) out = conv1x1(attn_out)  (hi/lo in, fp32 out), 4 tiles/CTA pipelined
    conv1x1_mma_k<<<dim3(32, 1, NB), 512, conv_smem>>>(aoh, aol, proj_w, proj_b, out, 128);
}

// round 14
// speedup vs baseline: 1.6725x; 1.0087x over previous
#include <cuda_runtime.h>
#include <cuda_bf16.h>
#include <math.h>
#include <stdint.h>

#define HW 16384      // 128*128
#define NB 8          // batch
#define LDA 136       // padded bf16 row stride (272B -> conflict-free ldmatrix rows)
#define TILEB (128 * LDA * 2)   // 34816 bytes per 128x128 bf16 tile

// Scratch (device globals; allocation inside kernel_launch is forbidden)
__device__ __nv_bfloat16 g_xh[16777216];      // x split hi
__device__ __nv_bfloat16 g_xl[16777216];      // x split lo
__device__ float g_qkv1[50331648];            // [8][384][16384] conv1x1 out (fp32)
__device__ __nv_bfloat16 g_aoh[16777216];     // attn out hi
__device__ __nv_bfloat16 g_aol[16777216];     // attn out lo

// ============================ helpers ==================================
__device__ __forceinline__ uint32_t smem_u32(const void* p) {
    uint32_t a;
    asm("{ .reg .u64 t; cvta.to.shared.u64 t, %1; cvt.u32.u64 %0, t; }" : "=r"(a) : "l"(p));
    return a;
}
__device__ __forceinline__ void ldsm4(uint32_t* r, uint32_t addr) {
    asm volatile("ldmatrix.sync.aligned.m8n8.x4.shared.b16 {%0,%1,%2,%3}, [%4];"
                 : "=r"(r[0]), "=r"(r[1]), "=r"(r[2]), "=r"(r[3]) : "r"(addr));
}
__device__ __forceinline__ void ldsm4_t(uint32_t* r, uint32_t addr) {
    asm volatile("ldmatrix.sync.aligned.m8n8.x4.trans.shared.b16 {%0,%1,%2,%3}, [%4];"
                 : "=r"(r[0]), "=r"(r[1]), "=r"(r[2]), "=r"(r[3]) : "r"(addr));
}
__device__ __forceinline__ void mma16816(float* d, const uint32_t* a, const uint32_t* b) {
    asm volatile("mma.sync.aligned.m16n8k16.row.col.f32.bf16.bf16.f32 "
        "{%0,%1,%2,%3}, {%4,%5,%6,%7}, {%8,%9}, {%0,%1,%2,%3};"
        : "+f"(d[0]), "+f"(d[1]), "+f"(d[2]), "+f"(d[3])
        : "r"(a[0]), "r"(a[1]), "r"(a[2]), "r"(a[3]), "r"(b[0]), "r"(b[1]));
}
__device__ __forceinline__ float bf2f(const void* p) {
    return __bfloat162float(*(const __nv_bfloat16*)p);
}
__device__ __forceinline__ void st_hilo_pair(char* th, char* tl, uint32_t off, float a, float b) {
    __nv_bfloat16 ah = __float2bfloat16(a), bh = __float2bfloat16(b);
    __nv_bfloat16 al = __float2bfloat16(a - __bfloat162float(ah));
    __nv_bfloat16 bl = __float2bfloat16(b - __bfloat162float(bh));
    __nv_bfloat162 ph; ph.x = ah; ph.y = bh;
    __nv_bfloat162 pl; pl.x = al; pl.y = bl;
    *(__nv_bfloat162*)(th + off) = ph;
    *(__nv_bfloat162*)(tl + off) = pl;
}
__device__ __forceinline__ void cpa16(uint32_t dst, const void* src) {
    asm volatile("cp.async.cg.shared.global [%0], [%1], 16;" :: "r"(dst), "l"(src));
}
#define CPA_COMMIT() asm volatile("cp.async.commit_group;" ::: "memory")
#define CPA_WAIT(n)  asm volatile("cp.async.wait_group %0;" :: "n"(n) : "memory")

// Merged split-precision K=128 pass: C += Ah*Bh + Ah*Bl + Al*Bh.
// Pass-major MMA order: 8 independent MMAs between accumulator reuses.
template<int AT, int BT>
__device__ __forceinline__ void gemm_triple(uint32_t aH, uint32_t aL,
                                            uint32_t bH, uint32_t bL,
                                            int m0, int n0, int lane, float c[2][4][4]) {
    #pragma unroll
    for (int ks = 0; ks < 8; ks++) {
        const int k0 = ks * 16;
        uint32_t ah[2][4], al[2][4];
        #pragma unroll
        for (int mt = 0; mt < 2; mt++) {
            uint32_t off;
            if (AT) {
                int krow = k0 + (lane & 7) + ((lane & 16) >> 1);
                int mcol = m0 + mt * 16 + (lane & 8);
                off = (uint32_t)((krow * LDA + mcol) * 2);
                ldsm4_t(ah[mt], aH + off);
                ldsm4_t(al[mt], aL + off);
            } else {
                int arow = m0 + mt * 16 + (lane & 15);
                int acol = k0 + ((lane >> 4) << 3);
                off = (uint32_t)((arow * LDA + acol) * 2);
                ldsm4(ah[mt], aH + off);
                ldsm4(al[mt], aL + off);
            }
        }
        uint32_t bh[4][2], bl[4][2];
        #pragma unroll
        for (int nb = 0; nb < 2; nb++) {
            uint32_t r[4], s[4], off;
            if (BT) {
                int krow = k0 + (lane & 7) + (lane & 8);
                int ncol = n0 + nb * 16 + ((lane & 16) >> 1);
                off = (uint32_t)((krow * LDA + ncol) * 2);
                ldsm4_t(r, bH + off);
                ldsm4_t(s, bL + off);
            } else {
                int nrow = n0 + nb * 16 + (lane & 7) + ((lane & 16) >> 1);
                int kcol = k0 + (lane & 8);
                off = (uint32_t)((nrow * LDA + kcol) * 2);
                ldsm4(r, bH + off);
                ldsm4(s, bL + off);
            }
            bh[2 * nb][0] = r[0];     bh[2 * nb][1] = r[1];
            bh[2 * nb + 1][0] = r[2]; bh[2 * nb + 1][1] = r[3];
            bl[2 * nb][0] = s[0];     bl[2 * nb][1] = s[1];
            bl[2 * nb + 1][0] = s[2]; bl[2 * nb + 1][1] = s[3];
        }
        #pragma unroll
        for (int mt = 0; mt < 2; mt++)
            #pragma unroll
            for (int nt = 0; nt < 4; nt++)
                mma16816(c[mt][nt], ah[mt], bh[nt]);
        #pragma unroll
        for (int mt = 0; mt < 2; mt++)
            #pragma unroll
            for (int nt = 0; nt < 4; nt++)
                mma16816(c[mt][nt], ah[mt], bl[nt]);
        #pragma unroll
        for (int mt = 0; mt < 2; mt++)
            #pragma unroll
            for (int nt = 0; nt < 4; nt++)
                mma16816(c[mt][nt], al[mt], bh[nt]);
    }
}

// ---------------------------------------------------------------------------
// split fp32 -> hi/lo bf16 planes. grid 4096, block 512, 8 floats/thread.
// ---------------------------------------------------------------------------
__global__ void __launch_bounds__(512, 2)
splitx_k(const float* __restrict__ x, __nv_bfloat16* __restrict__ xh,
         __nv_bfloat16* __restrict__ xl) {
    size_t i = ((size_t)blockIdx.x * 512 + threadIdx.x) * 8;
    float4 a = *(const float4*)(x + i);
    float4 b = *(const float4*)(x + i + 4);
    float v[8] = {a.x, a.y, a.z, a.w, b.x, b.y, b.z, b.w};
    uint32_t uh[4], ul[4];
    #pragma unroll
    for (int k = 0; k < 4; k++) {
        __nv_bfloat16 h0 = __float2bfloat16(v[2 * k]);
        __nv_bfloat16 h1 = __float2bfloat16(v[2 * k + 1]);
        __nv_bfloat162 ph; ph.x = h0; ph.y = h1;
        __nv_bfloat162 pl;
        pl.x = __float2bfloat16(v[2 * k] - __bfloat162float(h0));
        pl.y = __float2bfloat16(v[2 * k + 1] - __bfloat162float(h1));
        uh[k] = *(uint32_t*)&ph;
        ul[k] = *(uint32_t*)&pl;
    }
    *(uint4*)(xh + i) = *(uint4*)uh;
    *(uint4*)(xl + i) = *(uint4*)ul;
}

// ---------------------------------------------------------------------------
// conv1x1 via HMMA, 4 spatial tiles per CTA, cp.async double-buffered X.
// Y[oc,s] = W[oc,ic].X[ic,s] + bias; X given as hi/lo bf16 planes.
// grid (32 s-groups, OC/128, B), block 512 (16 warps, 32x32 warp tiles).
// ---------------------------------------------------------------------------
__global__ void __launch_bounds__(512, 1)
conv1x1_mma_k(const __nv_bfloat16* __restrict__ xbh, const __nv_bfloat16* __restrict__ xbl,
              const float* __restrict__ w, const float* __restrict__ bias,
              float* __restrict__ y, int OCtot) {
    extern __shared__ __align__(1024) char sm[];
    char* Wh = sm;
    char* Wl = sm + TILEB;
    __shared__ float biassm[128];

    const int tid = threadIdx.x;
    const int wid = tid >> 5, lane = tid & 31;
    const int sg  = blockIdx.x;
    const int oc0 = blockIdx.y * 128;
    const int b   = blockIdx.z;
    const uint32_t smb = smem_u32(sm);

    if (tid < 128) biassm[tid] = bias[oc0 + tid];

    {   // stage W once (convert fp32 -> hi/lo)
        const float4* wg = (const float4*)(w + (size_t)oc0 * 128);
        #pragma unroll
        for (int i = 0; i < 8; i++) {
            int idx4 = tid + i * 512;
            int r = idx4 >> 5, c4 = idx4 & 31;
            uint32_t o = (uint32_t)((r * LDA + 4 * c4) * 2);
            float4 v = wg[idx4];
            st_hilo_pair(Wh, Wl, o, v.x, v.y);
            st_hilo_pair(Wh, Wl, o + 4, v.z, v.w);
        }
    }

    const size_t xbase = (size_t)b * 128 * HW;

    auto issue_tile = [&](int t) {
        int bsel = t & 1;
        uint32_t bhs = smb + (uint32_t)(2 + 2 * bsel) * TILEB;
        uint32_t bls = bhs + TILEB;
        int s0 = sg * 512 + t * 128;
        const __nv_bfloat16* ph = xbh + xbase + s0;
        const __nv_bfloat16* pl = xbl + xbase + s0;
        #pragma unroll
        for (int i = 0; i < 4; i++) {
            int idx = tid + i * 512;
            int r = idx >> 4, c8 = idx & 15;
            uint32_t so = (uint32_t)(r * LDA * 2 + c8 * 16);
            size_t go = (size_t)r * HW + c8 * 8;
            cpa16(bhs + so, ph + go);
            cpa16(bls + so, pl + go);
        }
        CPA_COMMIT();
    };

    issue_tile(0);

    const int m0 = (wid & 3) * 32, n0 = (wid >> 2) * 32;
    const int g = lane >> 2, tg = lane & 3;
    const uint32_t aWh = smb, aWl = smb + TILEB;

    #pragma unroll
    for (int t = 0; t < 4; t++) {
        if (t < 3) issue_tile(t + 1);
        if (t < 3) { CPA_WAIT(1); } else { CPA_WAIT(0); }
        __syncthreads();

        float c[2][4][4];
        #pragma unroll
        for (int mt = 0; mt < 2; mt++)
            #pragma unroll
            for (int nt = 0; nt < 4; nt++)
                #pragma unroll
                for (int e = 0; e < 4; e++) c[mt][nt][e] = 0.f;

        uint32_t bhs = smb + (uint32_t)(2 + 2 * (t & 1)) * TILEB;
        gemm_triple<0, 1>(aWh, aWl, bhs, bhs + TILEB, m0, n0, lane, c);
        __syncthreads();

        float* stage = (float*)(sm + (size_t)(2 + 2 * (t & 1)) * TILEB);
        #pragma unroll
        for (int mt = 0; mt < 2; mt++) {
            int r0 = m0 + mt * 16 + g, r1 = r0 + 8;
            float b0 = biassm[r0], b1 = biassm[r1];
            #pragma unroll
            for (int nt = 0; nt < 4; nt++) {
                int col = n0 + nt * 8 + 2 * tg;
                float2 p0; p0.x = c[mt][nt][0] + b0; p0.y = c[mt][nt][1] + b0;
                *(float2*)&stage[r0 * 132 + col] = p0;
                float2 p1; p1.x = c[mt][nt][2] + b1; p1.y = c[mt][nt][3] + b1;
                *(float2*)&stage[r1 * 132 + col] = p1;
            }
        }
        __syncthreads();
        int s0 = sg * 512 + t * 128;
        float* yb = y + ((size_t)b * OCtot + oc0) * HW + s0;
        #pragma unroll
        for (int i = 0; i < 16; i++) {
            int idx = tid + i * 512;
            int row = idx >> 6, c2 = (idx & 63) * 2;
            *(float2*)&yb[(size_t)row * HW + c2] = *(float2*)&stage[row * 132 + c2];
        }
        __syncthreads();
    }
}

// ---------------------------------------------------------------------------
// Attention per (b,head,c); one CTA each (1024), block 512, HMMA triple.
// FUSED dwconv3x3: reads conv1 output (fp32), computes depthwise 3x3 + bias
// strip-by-strip through an fp32 smem buffer, writes hi/lo bf16 directly into
// the MMA tiles. Then: norms, GEMM1 (Lt = K^T Q), softmax, GEMM2 (V P).
// smem: 6 bf16 tiles (208896) + 34x128 fp32 strip (17408) = 226304.
// ---------------------------------------------------------------------------
__global__ void __launch_bounds__(512, 1)
attn_mma_k(const float* __restrict__ qkv1, const float* __restrict__ dw_w,
           const float* __restrict__ dw_b, const float* __restrict__ temp,
           __nv_bfloat16* __restrict__ oh, __nv_bfloat16* __restrict__ ol) {
    extern __shared__ __align__(1024) char sm[];
    char* Qh = sm;              char* Ql = sm + TILEB;
    char* Kh = sm + 2 * TILEB;  char* Kl = sm + 3 * TILEB;
    float* sbuf = (float*)(sm + 6 * (size_t)TILEB);   // [34][128] fp32 strip
    __shared__ float rqs[128], rnk[128], sinv[128];
    __shared__ float psum[4][128], rowsum[4][128];

    const int tid = threadIdx.x;
    const int wid = tid >> 5, lane = tid & 31;
    const int cid = blockIdx.x;
    const int qc  = cid & 127;
    const int b   = cid >> 7;
    const int hd  = qc >> 5;
    const uint32_t smb = smem_u32(sm);

    // ---- fused depthwise 3x3 into hi/lo tiles, 3 channels x 4 strips ----
    #pragma unroll 1
    for (int ch = 0; ch < 3; ch++) {
        const int cg = qc + ch * 128;                 // channel within 384
        const float* src = qkv1 + ((size_t)b * 384 + cg) * HW;
        float wv[9];
        #pragma unroll
        for (int i = 0; i < 9; i++) wv[i] = dw_w[cg * 9 + i];
        const float bi = dw_b[cg];
        char* th = sm + (size_t)(2 * ch) * TILEB;
        char* tl = th + TILEB;
        #pragma unroll 1
        for (int s = 0; s < 4; s++) {
            const int h0 = s * 32;
            __syncthreads();   // previous strip fully consumed
            for (int idx = tid; idx < 34 * 32; idx += 512) {   // 1088 float4
                int r = idx >> 5, c4 = idx & 31;
                int h = h0 - 1 + r;
                float4 v = (h >= 0 && h < 128) ? *(const float4*)(src + h * 128 + 4 * c4)
                                               : make_float4(0.f, 0.f, 0.f, 0.f);
                *(float4*)(sbuf + r * 128 + 4 * c4) = v;
            }
            __syncthreads();
            #pragma unroll
            for (int it = 0; it < 4; it++) {
                int idx = tid + it * 512;              // 2048 pairs
                int r = idx >> 6, col = (idx & 63) * 2;
                float a0 = bi, a1 = bi;
                #pragma unroll
                for (int dy = 0; dy < 3; dy++) {
                    #pragma unroll
                    for (int dx = 0; dx < 3; dx++) {
                        int c0 = col + dx - 1, c1 = c0 + 1;
                        float wgt = wv[dy * 3 + dx];
                        if (c0 >= 0) a0 = fmaf(wgt, sbuf[(r + dy) * 128 + c0], a0);
                        if (c1 < 128) a1 = fmaf(wgt, sbuf[(r + dy) * 128 + c1], a1);
                    }
                }
                st_hilo_pair(th, tl, (uint32_t)(((h0 + r) * LDA + col) * 2), a0, a1);
            }
        }
    }
    __syncthreads();

    // ---- column L2 norms over i, 4 groups of 128 threads ----
    {
        int col = tid & 127, gq = tid >> 7;
        const char* bh = (gq < 2) ? Qh : Kh;
        const char* bl = (gq < 2) ? Ql : Kl;
        int i0 = (gq & 1) * 64;
        float s = 0.f;
        #pragma unroll 8
        for (int i = 0; i < 64; i++) {
            uint32_t o = (uint32_t)(((i0 + i) * LDA + col) * 2);
            float xv = bf2f(bh + o) + bf2f(bl + o);
            s = fmaf(xv, xv, s);
        }
        psum[gq][col] = s;
    }
    __syncthreads();
    {
        const float tp = temp[hd];
        if (tid < 128)
            rqs[tid] = tp / fmaxf(sqrtf(psum[0][tid] + psum[1][tid]), 1e-12f);
        else if (tid < 256) {
            int c2 = tid - 128;
            rnk[c2] = 1.f / fmaxf(sqrtf(psum[2][c2] + psum[3][c2]), 1e-12f);
        }
    }
    __syncthreads();

    const int m0 = (wid & 3) * 32, n0 = (wid >> 2) * 32;
    float c[2][4][4];
    #pragma unroll
    for (int mt = 0; mt < 2; mt++)
        #pragma unroll
        for (int nt = 0; nt < 4; nt++)
            #pragma unroll
            for (int e = 0; e < 4; e++) c[mt][nt][e] = 0.f;

    // GEMM1: Lt[k][j] = sum_i K[i][k]*Q[i][j]
    gemm_triple<1, 1>(smb + 2 * TILEB, smb + 3 * TILEB, smb, smb + TILEB,
                      m0, n0, lane, c);

    // scale + exp in regs, row-partial sums
    const int g = lane >> 2, tg = lane & 3;
    float rs[4] = {0.f, 0.f, 0.f, 0.f};
    #pragma unroll
    for (int mt = 0; mt < 2; mt++) {
        int r0 = m0 + mt * 16 + g, r1 = r0 + 8;
        float k0s = rnk[r0], k1s = rnk[r1];
        #pragma unroll
        for (int nt = 0; nt < 4; nt++) {
            int j0 = n0 + nt * 8 + 2 * tg;
            float q0 = rqs[j0], q1 = rqs[j0 + 1];
            float e0 = __expf(c[mt][nt][0] * k0s * q0);
            float e1 = __expf(c[mt][nt][1] * k0s * q1);
            float e2 = __expf(c[mt][nt][2] * k1s * q0);
            float e3 = __expf(c[mt][nt][3] * k1s * q1);
            c[mt][nt][0] = e0; c[mt][nt][1] = e1;
            c[mt][nt][2] = e2; c[mt][nt][3] = e3;
            rs[2 * mt] += e0 + e1;
            rs[2 * mt + 1] += e2 + e3;
        }
    }
    __syncthreads();   // GEMM1 reads done

    // store P^T into K tile space; finish row sums
    #pragma unroll
    for (int mt = 0; mt < 2; mt++) {
        int r0 = m0 + mt * 16 + g, r1 = r0 + 8;
        #pragma unroll
        for (int nt = 0; nt < 4; nt++) {
            int j0 = n0 + nt * 8 + 2 * tg;
            st_hilo_pair(Kh, Kl, (uint32_t)((r0 * LDA + j0) * 2), c[mt][nt][0], c[mt][nt][1]);
            st_hilo_pair(Kh, Kl, (uint32_t)((r1 * LDA + j0) * 2), c[mt][nt][2], c[mt][nt][3]);
        }
    }
    #pragma unroll
    for (int i = 0; i < 4; i++) {
        rs[i] += __shfl_xor_sync(0xFFFFFFFFu, rs[i], 1);
        rs[i] += __shfl_xor_sync(0xFFFFFFFFu, rs[i], 2);
    }
    if (tg == 0) {
        int grp = wid >> 2;
        rowsum[grp][m0 + g]      = rs[0];
        rowsum[grp][m0 + 8 + g]  = rs[1];
        rowsum[grp][m0 + 16 + g] = rs[2];
        rowsum[grp][m0 + 24 + g] = rs[3];
    }
    __syncthreads();
    if (tid < 128)
        sinv[tid] = 1.f / (rowsum[0][tid] + rowsum[1][tid] + rowsum[2][tid] + rowsum[3][tid]);

    // GEMM2: D2[i][k] = sum_j V[i][j]*P[j][k]
    #pragma unroll
    for (int mt = 0; mt < 2; mt++)
        #pragma unroll
        for (int nt = 0; nt < 4; nt++)
            #pragma unroll
            for (int e = 0; e < 4; e++) c[mt][nt][e] = 0.f;
    gemm_triple<0, 0>(smb + 4 * TILEB, smb + 5 * TILEB, smb + 2 * TILEB, smb + 3 * TILEB,
                      m0, n0, lane, c);
    __syncthreads();   // sinv visible; Q tiles free

    float* stage = (float*)Qh;   // [128][132]
    #pragma unroll
    for (int mt = 0; mt < 2; mt++) {
        int r0 = m0 + mt * 16 + g, r1 = r0 + 8;
        #pragma unroll
        for (int nt = 0; nt < 4; nt++) {
            int col = n0 + nt * 8 + 2 * tg;
            float s0 = sinv[col], s1 = sinv[col + 1];
            float2 p0; p0.x = c[mt][nt][0] * s0; p0.y = c[mt][nt][1] * s1;
            *(float2*)&stage[r0 * 132 + col] = p0;
            float2 p1; p1.x = c[mt][nt][2] * s0; p1.y = c[mt][nt][3] * s1;
            *(float2*)&stage[r1 * 132 + col] = p1;
        }
    }
    __syncthreads();
    const size_t ob = ((size_t)b * 128 + qc) * HW;
    #pragma unroll
    for (int i = 0; i < 16; i++) {
        int idx = tid + i * 512;
        int row = idx >> 6, c2 = (idx & 63) * 2;
        float2 v = *(float2*)&stage[row * 132 + c2];
        __nv_bfloat16 h0b = __float2bfloat16(v.x), h1b = __float2bfloat16(v.y);
        __nv_bfloat162 ph; ph.x = h0b; ph.y = h1b;
        __nv_bfloat162 pl;
        pl.x = __float2bfloat16(v.x - __bfloat162float(h0b));
        pl.y = __float2bfloat16(v.y - __bfloat162float(h1b));
        *(__nv_bfloat162*)&oh[ob + row * 128 + c2] = ph;
        *(__nv_bfloat162*)&ol[ob + row * 128 + c2] = pl;
    }
}

// ---------------------------------------------------------------------------
extern "C" void kernel_launch(void* const* d_in, const int* in_sizes, int n_in,
                              void* d_out, int out_size) {
    const float* x      = (const float*)d_in[0];
    const float* qkv_w  = (const float*)d_in[1];
    const float* qkv_b  = (const float*)d_in[2];
    const float* dw_w   = (const float*)d_in[3];
    const float* dw_b   = (const float*)d_in[4];
    const float* proj_w = (const float*)d_in[5];
    const float* proj_b = (const float*)d_in[6];
    const float* temp   = (const float*)d_in[7];
    float* out = (float*)d_out;

    void *pxh, *pxl, *p1, *p3h, *p3l;
    cudaGetSymbolAddress(&pxh, g_xh);
    cudaGetSymbolAddress(&pxl, g_xl);
    cudaGetSymbolAddress(&p1, g_qkv1);
    cudaGetSymbolAddress(&p3h, g_aoh);
    cudaGetSymbolAddress(&p3l, g_aol);
    __nv_bfloat16* xh = (__nv_bfloat16*)pxh;
    __nv_bfloat16* xl = (__nv_bfloat16*)pxl;
    float* qkv1 = (float*)p1;
    __nv_bfloat16* aoh = (__nv_bfloat16*)p3h;
    __nv_bfloat16* aol = (__nv_bfloat16*)p3l;

    const int conv_smem = 6 * TILEB;              // 208896
    const int attn_smem = 6 * TILEB + 34 * 128 * 4;  // 226304
    cudaFuncSetAttribute(conv1x1_mma_k, cudaFuncAttributeMaxDynamicSharedMemorySize, conv_smem);
    cudaFuncSetAttribute(attn_mma_k,    cudaFuncAttributeMaxDynamicSharedMemorySize, attn_smem);

    // 0) split x into hi/lo bf16 planes
    splitx_k<<<4096, 512>>>(x, xh, xl);
    // 1) qkv = conv1x1(x)  (hi/lo in, fp32 out), 4 tiles/CTA pipelined
    conv1x1_mma_k<<<dim3(32, 3, NB), 512, conv_smem>>>(xh, xl, qkv_w, qkv_b, qkv1, 384);
    // 2+3) fused dwconv3x3 + transposed attention (fp32 in, hi/lo out)
    attn_mma_k<<<dim3(1024), 512, attn_smem>>>(qkv1, dw_w, dw_b, temp, aoh, aol);
    // 4) out = conv1x1(attn_out)  (hi/lo in, fp32 out), 4 tiles/CTA pipelined
    conv1x1_mma_k<<<dim3(32, 1, NB), 512, conv_smem>>>(aoh, aol, proj_w, proj_b, out, 128);
}

// round 15
// speedup vs baseline: 2.0623x; 1.2331x over previous
#include <cuda_runtime.h>
#include <cuda_bf16.h>
#include <math.h>
#include <stdint.h>

#define HW 16384      // 128*128
#define NB 8          // batch
#define LDA 136       // padded bf16 row stride (272B -> conflict-free ldmatrix rows)
#define TILEB (128 * LDA * 2)   // 34816 bytes per 128x128 bf16 tile

// Scratch (device globals; allocation inside kernel_launch is forbidden)
__device__ __nv_bfloat16 g_xh[16777216];      // x split hi
__device__ __nv_bfloat16 g_xl[16777216];      // x split lo
__device__ float g_qkv1[50331648];            // [8][384][16384] conv1x1 out (fp32)
__device__ __nv_bfloat16 g_aoh[16777216];     // attn out hi
__device__ __nv_bfloat16 g_aol[16777216];     // attn out lo

// ============================ helpers ==================================
__device__ __forceinline__ uint32_t smem_u32(const void* p) {
    uint32_t a;
    asm("{ .reg .u64 t; cvta.to.shared.u64 t, %1; cvt.u32.u64 %0, t; }" : "=r"(a) : "l"(p));
    return a;
}
__device__ __forceinline__ void ldsm4(uint32_t* r, uint32_t addr) {
    asm volatile("ldmatrix.sync.aligned.m8n8.x4.shared.b16 {%0,%1,%2,%3}, [%4];"
                 : "=r"(r[0]), "=r"(r[1]), "=r"(r[2]), "=r"(r[3]) : "r"(addr));
}
__device__ __forceinline__ void ldsm4_t(uint32_t* r, uint32_t addr) {
    asm volatile("ldmatrix.sync.aligned.m8n8.x4.trans.shared.b16 {%0,%1,%2,%3}, [%4];"
                 : "=r"(r[0]), "=r"(r[1]), "=r"(r[2]), "=r"(r[3]) : "r"(addr));
}
__device__ __forceinline__ void mma16816(float* d, const uint32_t* a, const uint32_t* b) {
    asm volatile("mma.sync.aligned.m16n8k16.row.col.f32.bf16.bf16.f32 "
        "{%0,%1,%2,%3}, {%4,%5,%6,%7}, {%8,%9}, {%0,%1,%2,%3};"
        : "+f"(d[0]), "+f"(d[1]), "+f"(d[2]), "+f"(d[3])
        : "r"(a[0]), "r"(a[1]), "r"(a[2]), "r"(a[3]), "r"(b[0]), "r"(b[1]));
}
__device__ __forceinline__ float bf2f(const void* p) {
    return __bfloat162float(*(const __nv_bfloat16*)p);
}
__device__ __forceinline__ void st_hilo_pair(char* th, char* tl, uint32_t off, float a, float b) {
    __nv_bfloat16 ah = __float2bfloat16(a), bh = __float2bfloat16(b);
    __nv_bfloat16 al = __float2bfloat16(a - __bfloat162float(ah));
    __nv_bfloat16 bl = __float2bfloat16(b - __bfloat162float(bh));
    __nv_bfloat162 ph; ph.x = ah; ph.y = bh;
    __nv_bfloat162 pl; pl.x = al; pl.y = bl;
    *(__nv_bfloat162*)(th + off) = ph;
    *(__nv_bfloat162*)(tl + off) = pl;
}
__device__ __forceinline__ void cpa16(uint32_t dst, const void* src) {
    asm volatile("cp.async.cg.shared.global [%0], [%1], 16;" :: "r"(dst), "l"(src));
}
#define CPA_COMMIT() asm volatile("cp.async.commit_group;" ::: "memory")
#define CPA_WAIT(n)  asm volatile("cp.async.wait_group %0;" :: "n"(n) : "memory")

// Merged split-precision K=128 pass: C += Ah*Bh + Ah*Bl + Al*Bh.
template<int AT, int BT>
__device__ __forceinline__ void gemm_triple(uint32_t aH, uint32_t aL,
                                            uint32_t bH, uint32_t bL,
                                            int m0, int n0, int lane, float c[2][4][4]) {
    #pragma unroll
    for (int ks = 0; ks < 8; ks++) {
        const int k0 = ks * 16;
        uint32_t ah[2][4], al[2][4];
        #pragma unroll
        for (int mt = 0; mt < 2; mt++) {
            uint32_t off;
            if (AT) {
                int krow = k0 + (lane & 7) + ((lane & 16) >> 1);
                int mcol = m0 + mt * 16 + (lane & 8);
                off = (uint32_t)((krow * LDA + mcol) * 2);
                ldsm4_t(ah[mt], aH + off);
                ldsm4_t(al[mt], aL + off);
            } else {
                int arow = m0 + mt * 16 + (lane & 15);
                int acol = k0 + ((lane >> 4) << 3);
                off = (uint32_t)((arow * LDA + acol) * 2);
                ldsm4(ah[mt], aH + off);
                ldsm4(al[mt], aL + off);
            }
        }
        uint32_t bh[4][2], bl[4][2];
        #pragma unroll
        for (int nb = 0; nb < 2; nb++) {
            uint32_t r[4], s[4], off;
            if (BT) {
                int krow = k0 + (lane & 7) + (lane & 8);
                int ncol = n0 + nb * 16 + ((lane & 16) >> 1);
                off = (uint32_t)((krow * LDA + ncol) * 2);
                ldsm4_t(r, bH + off);
                ldsm4_t(s, bL + off);
            } else {
                int nrow = n0 + nb * 16 + (lane & 7) + ((lane & 16) >> 1);
                int kcol = k0 + (lane & 8);
                off = (uint32_t)((nrow * LDA + kcol) * 2);
                ldsm4(r, bH + off);
                ldsm4(s, bL + off);
            }
            bh[2 * nb][0] = r[0];     bh[2 * nb][1] = r[1];
            bh[2 * nb + 1][0] = r[2]; bh[2 * nb + 1][1] = r[3];
            bl[2 * nb][0] = s[0];     bl[2 * nb][1] = s[1];
            bl[2 * nb + 1][0] = s[2]; bl[2 * nb + 1][1] = s[3];
        }
        #pragma unroll
        for (int mt = 0; mt < 2; mt++)
            #pragma unroll
            for (int nt = 0; nt < 4; nt++)
                mma16816(c[mt][nt], ah[mt], bh[nt]);
        #pragma unroll
        for (int mt = 0; mt < 2; mt++)
            #pragma unroll
            for (int nt = 0; nt < 4; nt++)
                mma16816(c[mt][nt], ah[mt], bl[nt]);
        #pragma unroll
        for (int mt = 0; mt < 2; mt++)
            #pragma unroll
            for (int nt = 0; nt < 4; nt++)
                mma16816(c[mt][nt], al[mt], bh[nt]);
    }
}

// ---------------------------------------------------------------------------
// split fp32 -> hi/lo bf16 planes. grid 4096, block 512, 8 floats/thread.
// ---------------------------------------------------------------------------
__global__ void __launch_bounds__(512, 2)
splitx_k(const float* __restrict__ x, __nv_bfloat16* __restrict__ xh,
         __nv_bfloat16* __restrict__ xl) {
    size_t i = ((size_t)blockIdx.x * 512 + threadIdx.x) * 8;
    float4 a = *(const float4*)(x + i);
    float4 b = *(const float4*)(x + i + 4);
    float v[8] = {a.x, a.y, a.z, a.w, b.x, b.y, b.z, b.w};
    uint32_t uh[4], ul[4];
    #pragma unroll
    for (int k = 0; k < 4; k++) {
        __nv_bfloat16 h0 = __float2bfloat16(v[2 * k]);
        __nv_bfloat16 h1 = __float2bfloat16(v[2 * k + 1]);
        __nv_bfloat162 ph; ph.x = h0; ph.y = h1;
        __nv_bfloat162 pl;
        pl.x = __float2bfloat16(v[2 * k] - __bfloat162float(h0));
        pl.y = __float2bfloat16(v[2 * k + 1] - __bfloat162float(h1));
        uh[k] = *(uint32_t*)&ph;
        ul[k] = *(uint32_t*)&pl;
    }
    *(uint4*)(xh + i) = *(uint4*)uh;
    *(uint4*)(xl + i) = *(uint4*)ul;
}

// ---------------------------------------------------------------------------
// PERSISTENT conv1x1 via HMMA. Each CTA: fixed oc-block, W staged once, loops
// over spatial jobs (b, s-tile) with stride = gridDim.x, cp.async double-buffer
// running continuously across the whole loop (no drains, no wave tails).
// jobs: 0..1023 -> b = job>>7, s0 = (job&127)*128.
// ---------------------------------------------------------------------------
__global__ void __launch_bounds__(512, 1)
conv1x1_mma_k(const __nv_bfloat16* __restrict__ xbh, const __nv_bfloat16* __restrict__ xbl,
              const float* __restrict__ w, const float* __restrict__ bias,
              float* __restrict__ y, int OCtot) {
    extern __shared__ __align__(1024) char sm[];
    char* Wh = sm;
    char* Wl = sm + TILEB;
    __shared__ float biassm[128];

    const int tid = threadIdx.x;
    const int wid = tid >> 5, lane = tid & 31;
    const int oc0 = blockIdx.y * 128;
    const int stride = gridDim.x;
    const uint32_t smb = smem_u32(sm);

    if (tid < 128) biassm[tid] = bias[oc0 + tid];

    {   // stage W once (convert fp32 -> hi/lo)
        const float4* wg = (const float4*)(w + (size_t)oc0 * 128);
        #pragma unroll
        for (int i = 0; i < 8; i++) {
            int idx4 = tid + i * 512;
            int r = idx4 >> 5, c4 = idx4 & 31;
            uint32_t o = (uint32_t)((r * LDA + 4 * c4) * 2);
            float4 v = wg[idx4];
            st_hilo_pair(Wh, Wl, o, v.x, v.y);
            st_hilo_pair(Wh, Wl, o + 4, v.z, v.w);
        }
    }

    auto issue_job = [&](int job, int parity) {
        uint32_t bhs = smb + (uint32_t)(2 + 2 * parity) * TILEB;
        uint32_t bls = bhs + TILEB;
        int b = job >> 7, s0 = (job & 127) << 7;
        const __nv_bfloat16* ph = xbh + (size_t)b * 128 * HW + s0;
        const __nv_bfloat16* pl = xbl + (size_t)b * 128 * HW + s0;
        #pragma unroll
        for (int i = 0; i < 4; i++) {
            int idx = tid + i * 512;
            int r = idx >> 4, c8 = idx & 15;
            uint32_t so = (uint32_t)(r * LDA * 2 + c8 * 16);
            size_t go = (size_t)r * HW + c8 * 8;
            cpa16(bhs + so, ph + go);
            cpa16(bls + so, pl + go);
        }
        CPA_COMMIT();
    };

    const int m0 = (wid & 3) * 32, n0 = (wid >> 2) * 32;
    const int g = lane >> 2, tg = lane & 3;
    const uint32_t aWh = smb, aWl = smb + TILEB;

    int par = 0;
    if (blockIdx.x < 1024) issue_job(blockIdx.x, 0);
    for (int job = blockIdx.x; job < 1024; job += stride, par ^= 1) {
        int nxt = job + stride;
        if (nxt < 1024) { issue_job(nxt, par ^ 1); CPA_WAIT(1); }
        else            { CPA_WAIT(0); }
        __syncthreads();

        float c[2][4][4];
        #pragma unroll
        for (int mt = 0; mt < 2; mt++)
            #pragma unroll
            for (int nt = 0; nt < 4; nt++)
                #pragma unroll
                for (int e = 0; e < 4; e++) c[mt][nt][e] = 0.f;

        uint32_t bhs = smb + (uint32_t)(2 + 2 * par) * TILEB;
        gemm_triple<0, 1>(aWh, aWl, bhs, bhs + TILEB, m0, n0, lane, c);
        __syncthreads();   // buffer reads done -> overlay as fp32 stage

        float* stage = (float*)(sm + (size_t)(2 + 2 * par) * TILEB);
        #pragma unroll
        for (int mt = 0; mt < 2; mt++) {
            int r0 = m0 + mt * 16 + g, r1 = r0 + 8;
            float b0 = biassm[r0], b1 = biassm[r1];
            #pragma unroll
            for (int nt = 0; nt < 4; nt++) {
                int col = n0 + nt * 8 + 2 * tg;
                float2 p0; p0.x = c[mt][nt][0] + b0; p0.y = c[mt][nt][1] + b0;
                *(float2*)&stage[r0 * 132 + col] = p0;
                float2 p1; p1.x = c[mt][nt][2] + b1; p1.y = c[mt][nt][3] + b1;
                *(float2*)&stage[r1 * 132 + col] = p1;
            }
        }
        __syncthreads();
        int b = job >> 7, s0 = (job & 127) << 7;
        float* yb = y + ((size_t)b * OCtot + oc0) * HW + s0;
        #pragma unroll
        for (int i = 0; i < 16; i++) {
            int idx = tid + i * 512;
            int row = idx >> 6, c2 = (idx & 63) * 2;
            *(float2*)&yb[(size_t)row * HW + c2] = *(float2*)&stage[row * 132 + c2];
        }
        __syncthreads();   // stage reads done before cp.async reuses this buffer
    }
}

// ---------------------------------------------------------------------------
// Attention per (b,head,c); one CTA each (1024), block 512, HMMA triple.
// FUSED dwconv3x3 with REGISTER-PREFETCHED strips: while strip t is computed
// from smem, strip t+1's gmem loads are already in flight into registers.
// 12 strips total (3 channels x 4). Then norms, GEMM1, softmax, GEMM2.
// ---------------------------------------------------------------------------
__global__ void __launch_bounds__(512, 1)
attn_mma_k(const float* __restrict__ qkv1, const float* __restrict__ dw_w,
           const float* __restrict__ dw_b, const float* __restrict__ temp,
           __nv_bfloat16* __restrict__ oh, __nv_bfloat16* __restrict__ ol) {
    extern __shared__ __align__(1024) char sm[];
    char* Qh = sm;              char* Ql = sm + TILEB;
    char* Kh = sm + 2 * TILEB;  char* Kl = sm + 3 * TILEB;
    float* sbuf = (float*)(sm + 6 * (size_t)TILEB);   // [34][128] fp32 strip
    __shared__ float rqs[128], rnk[128], sinv[128];
    __shared__ float psum[4][128], rowsum[4][128];

    const int tid = threadIdx.x;
    const int wid = tid >> 5, lane = tid & 31;
    const int cid = blockIdx.x;
    const int qc  = cid & 127;
    const int b   = cid >> 7;
    const int hd  = qc >> 5;
    const uint32_t smb = smem_u32(sm);

    // ---- fused depthwise 3x3, 12 strips, register prefetch ----
    // per strip: 34 rows x 32 float4; thread covers idx = tid, tid+512, tid+1024(<1088)
    auto ld_strip = [&](int t, float4* pre) {
        int ch = t >> 2, s = t & 3;
        int cg = qc + (ch << 7);
        const float* src = qkv1 + ((size_t)b * 384 + cg) * HW;
        int h0 = (s << 5) - 1;
        #pragma unroll
        for (int i = 0; i < 3; i++) {
            int idx = tid + i * 512;
            if (idx < 1088) {
                int r = idx >> 5, c4 = idx & 31;
                int h = h0 + r;
                pre[i] = (h >= 0 && h < 128) ? *(const float4*)(src + h * 128 + 4 * c4)
                                             : make_float4(0.f, 0.f, 0.f, 0.f);
            }
        }
    };
    auto st_strip = [&](const float4* pre) {
        #pragma unroll
        for (int i = 0; i < 3; i++) {
            int idx = tid + i * 512;
            if (idx < 1088) {
                int r = idx >> 5, c4 = idx & 31;
                *(float4*)(sbuf + r * 128 + 4 * c4) = pre[i];
            }
        }
    };

    float4 p0[3], p1[3];
    ld_strip(0, p0);
    #pragma unroll
    for (int t = 0; t < 12; t++) {
        const int ch = t >> 2, s = t & 3;
        const int cg = qc + (ch << 7);
        const int h0 = s << 5;
        float wv[9];
        #pragma unroll
        for (int i = 0; i < 9; i++) wv[i] = dw_w[cg * 9 + i];
        const float bi = dw_b[cg];
        char* th = sm + (size_t)(2 * ch) * TILEB;
        char* tl = th + TILEB;

        __syncthreads();                     // prev strip compute done
        if (t & 1) st_strip(p1); else st_strip(p0);
        if (t < 11) { if (t & 1) ld_strip(t + 1, p0); else ld_strip(t + 1, p1); }
        __syncthreads();                     // sbuf ready

        #pragma unroll
        for (int it = 0; it < 4; it++) {
            int idx = tid + it * 512;
            int r = idx >> 6, col = (idx & 63) * 2;
            float a0 = bi, a1 = bi;
            #pragma unroll
            for (int dy = 0; dy < 3; dy++) {
                #pragma unroll
                for (int dx = 0; dx < 3; dx++) {
                    int c0 = col + dx - 1, c1 = c0 + 1;
                    float wgt = wv[dy * 3 + dx];
                    if (c0 >= 0) a0 = fmaf(wgt, sbuf[(r + dy) * 128 + c0], a0);
                    if (c1 < 128) a1 = fmaf(wgt, sbuf[(r + dy) * 128 + c1], a1);
                }
            }
            st_hilo_pair(th, tl, (uint32_t)(((h0 + r) * LDA + col) * 2), a0, a1);
        }
    }
    __syncthreads();

    // ---- column L2 norms over i, 4 groups of 128 threads ----
    {
        int col = tid & 127, gq = tid >> 7;
        const char* bh = (gq < 2) ? Qh : Kh;
        const char* bl = (gq < 2) ? Ql : Kl;
        int i0 = (gq & 1) * 64;
        float s = 0.f;
        #pragma unroll 8
        for (int i = 0; i < 64; i++) {
            uint32_t o = (uint32_t)(((i0 + i) * LDA + col) * 2);
            float xv = bf2f(bh + o) + bf2f(bl + o);
            s = fmaf(xv, xv, s);
        }
        psum[gq][col] = s;
    }
    __syncthreads();
    {
        const float tp = temp[hd];
        if (tid < 128)
            rqs[tid] = tp / fmaxf(sqrtf(psum[0][tid] + psum[1][tid]), 1e-12f);
        else if (tid < 256) {
            int c2 = tid - 128;
            rnk[c2] = 1.f / fmaxf(sqrtf(psum[2][c2] + psum[3][c2]), 1e-12f);
        }
    }
    __syncthreads();

    const int m0 = (wid & 3) * 32, n0 = (wid >> 2) * 32;
    float c[2][4][4];
    #pragma unroll
    for (int mt = 0; mt < 2; mt++)
        #pragma unroll
        for (int nt = 0; nt < 4; nt++)
            #pragma unroll
            for (int e = 0; e < 4; e++) c[mt][nt][e] = 0.f;

    // GEMM1: Lt[k][j] = sum_i K[i][k]*Q[i][j]
    gemm_triple<1, 1>(smb + 2 * TILEB, smb + 3 * TILEB, smb, smb + TILEB,
                      m0, n0, lane, c);

    // scale + exp in regs, row-partial sums
    const int g = lane >> 2, tg = lane & 3;
    float rs[4] = {0.f, 0.f, 0.f, 0.f};
    #pragma unroll
    for (int mt = 0; mt < 2; mt++) {
        int r0 = m0 + mt * 16 + g, r1 = r0 + 8;
        float k0s = rnk[r0], k1s = rnk[r1];
        #pragma unroll
        for (int nt = 0; nt < 4; nt++) {
            int j0 = n0 + nt * 8 + 2 * tg;
            float q0 = rqs[j0], q1 = rqs[j0 + 1];
            float e0 = __expf(c[mt][nt][0] * k0s * q0);
            float e1 = __expf(c[mt][nt][1] * k0s * q1);
            float e2 = __expf(c[mt][nt][2] * k1s * q0);
            float e3 = __expf(c[mt][nt][3] * k1s * q1);
            c[mt][nt][0] = e0; c[mt][nt][1] = e1;
            c[mt][nt][2] = e2; c[mt][nt][3] = e3;
            rs[2 * mt] += e0 + e1;
            rs[2 * mt + 1] += e2 + e3;
        }
    }
    __syncthreads();   // GEMM1 reads done

    // store P^T into K tile space; finish row sums
    #pragma unroll
    for (int mt = 0; mt < 2; mt++) {
        int r0 = m0 + mt * 16 + g, r1 = r0 + 8;
        #pragma unroll
        for (int nt = 0; nt < 4; nt++) {
            int j0 = n0 + nt * 8 + 2 * tg;
            st_hilo_pair(Kh, Kl, (uint32_t)((r0 * LDA + j0) * 2), c[mt][nt][0], c[mt][nt][1]);
            st_hilo_pair(Kh, Kl, (uint32_t)((r1 * LDA + j0) * 2), c[mt][nt][2], c[mt][nt][3]);
        }
    }
    #pragma unroll
    for (int i = 0; i < 4; i++) {
        rs[i] += __shfl_xor_sync(0xFFFFFFFFu, rs[i], 1);
        rs[i] += __shfl_xor_sync(0xFFFFFFFFu, rs[i], 2);
    }
    if (tg == 0) {
        int grp = wid >> 2;
        rowsum[grp][m0 + g]      = rs[0];
        rowsum[grp][m0 + 8 + g]  = rs[1];
        rowsum[grp][m0 + 16 + g] = rs[2];
        rowsum[grp][m0 + 24 + g] = rs[3];
    }
    __syncthreads();
    if (tid < 128)
        sinv[tid] = 1.f / (rowsum[0][tid] + rowsum[1][tid] + rowsum[2][tid] + rowsum[3][tid]);

    // GEMM2: D2[i][k] = sum_j V[i][j]*P[j][k]
    #pragma unroll
    for (int mt = 0; mt < 2; mt++)
        #pragma unroll
        for (int nt = 0; nt < 4; nt++)
            #pragma unroll
            for (int e = 0; e < 4; e++) c[mt][nt][e] = 0.f;
    gemm_triple<0, 0>(smb + 4 * TILEB, smb + 5 * TILEB, smb + 2 * TILEB, smb + 3 * TILEB,
                      m0, n0, lane, c);
    __syncthreads();   // sinv visible; Q tiles free

    float* stage = (float*)Qh;   // [128][132]
    #pragma unroll
    for (int mt = 0; mt < 2; mt++) {
        int r0 = m0 + mt * 16 + g, r1 = r0 + 8;
        #pragma unroll
        for (int nt = 0; nt < 4; nt++) {
            int col = n0 + nt * 8 + 2 * tg;
            float s0 = sinv[col], s1 = sinv[col + 1];
            float2 pp0; pp0.x = c[mt][nt][0] * s0; pp0.y = c[mt][nt][1] * s1;
            *(float2*)&stage[r0 * 132 + col] = pp0;
            float2 pp1; pp1.x = c[mt][nt][2] * s0; pp1.y = c[mt][nt][3] * s1;
            *(float2*)&stage[r1 * 132 + col] = pp1;
        }
    }
    __syncthreads();
    const size_t ob = ((size_t)b * 128 + qc) * HW;
    #pragma unroll
    for (int i = 0; i < 16; i++) {
        int idx = tid + i * 512;
        int row = idx >> 6, c2 = (idx & 63) * 2;
        float2 v = *(float2*)&stage[row * 132 + c2];
        __nv_bfloat16 h0b = __float2bfloat16(v.x), h1b = __float2bfloat16(v.y);
        __nv_bfloat162 ph; ph.x = h0b; ph.y = h1b;
        __nv_bfloat162 pl;
        pl.x = __float2bfloat16(v.x - __bfloat162float(h0b));
        pl.y = __float2bfloat16(v.y - __bfloat162float(h1b));
        *(__nv_bfloat162*)&oh[ob + row * 128 + c2] = ph;
        *(__nv_bfloat162*)&ol[ob + row * 128 + c2] = pl;
    }
}

// ---------------------------------------------------------------------------
extern "C" void kernel_launch(void* const* d_in, const int* in_sizes, int n_in,
                              void* d_out, int out_size) {
    const float* x      = (const float*)d_in[0];
    const float* qkv_w  = (const float*)d_in[1];
    const float* qkv_b  = (const float*)d_in[2];
    const float* dw_w   = (const float*)d_in[3];
    const float* dw_b   = (const float*)d_in[4];
    const float* proj_w = (const float*)d_in[5];
    const float* proj_b = (const float*)d_in[6];
    const float* temp   = (const float*)d_in[7];
    float* out = (float*)d_out;

    void *pxh, *pxl, *p1, *p3h, *p3l;
    cudaGetSymbolAddress(&pxh, g_xh);
    cudaGetSymbolAddress(&pxl, g_xl);
    cudaGetSymbolAddress(&p1, g_qkv1);
    cudaGetSymbolAddress(&p3h, g_aoh);
    cudaGetSymbolAddress(&p3l, g_aol);
    __nv_bfloat16* xh = (__nv_bfloat16*)pxh;
    __nv_bfloat16* xl = (__nv_bfloat16*)pxl;
    float* qkv1 = (float*)p1;
    __nv_bfloat16* aoh = (__nv_bfloat16*)p3h;
    __nv_bfloat16* aol = (__nv_bfloat16*)p3l;

    const int conv_smem = 6 * TILEB;                 // 208896
    const int attn_smem = 6 * TILEB + 34 * 128 * 4;  // 226304
    cudaFuncSetAttribute(conv1x1_mma_k, cudaFuncAttributeMaxDynamicSharedMemorySize, conv_smem);
    cudaFuncSetAttribute(attn_mma_k,    cudaFuncAttributeMaxDynamicSharedMemorySize, attn_smem);

    // 0) split x into hi/lo bf16 planes
    splitx_k<<<4096, 512>>>(x, xh, xl);
    // 1) qkv = conv1x1(x): persistent, one wave (147 CTAs), ~21 jobs each
    conv1x1_mma_k<<<dim3(49, 3, 1), 512, conv_smem>>>(xh, xl, qkv_w, qkv_b, qkv1, 384);
    // 2+3) fused dwconv3x3 + transposed attention (fp32 in, hi/lo out)
    attn_mma_k<<<dim3(1024), 512, attn_smem>>>(qkv1, dw_w, dw_b, temp, aoh, aol);
    // 4) out = conv1x1(attn_out): persistent, one wave (148 CTAs), ~7 jobs each
    conv1x1_mma_k<<<dim3(148, 1, 1), 512, conv_smem>>>(aoh, aol, proj_w, proj_b, out, 128);
}